// round 10
// baseline (speedup 1.0000x reference)
#include <cuda_runtime.h>
#include <cuda_fp16.h>
#include <math.h>
#include <stdint.h>

#define B_    4
#define LQ_   4096
#define LKV_  256
#define D_    1024
#define H_    16
#define KVH_  4
#define HD_   64
#define NF_MAX 4096

// ---------------- scratch (device globals; no allocation allowed) ----------
__device__ __half g_Ph[(size_t)B_ * LQ_ * D_];          // fp16 patches
__device__ __half g_Lh[(size_t)B_ * LKV_ * D_];         // fp16 latents
__device__ __half g_Q[(size_t)B_ * LQ_ * D_];           // fp16 Q
__device__ __half g_KV[(size_t)B_ * LKV_ * 512];        // fused K|V
__device__ __half g_attn[(size_t)B_ * LQ_ * D_];        // fp16 attn out
__device__ __half g_WtQ[(size_t)D_ * D_];               // W^T [N][K] fp16
__device__ __half g_WtKV[(size_t)512 * D_];             // [Wk^T ; Wv^T]
__device__ __half g_WtO[(size_t)D_ * D_];
__device__ float  g_bkv[512];                            // bk | bv
__device__ float  g_rope[2 * NF_MAX * 32];              // cos | sin

// ---------------- helpers ---------------------------------------------------
__device__ __forceinline__ uint32_t smem_u32(const void* p) {
    uint32_t a;
    asm("{ .reg .u64 t; cvta.to.shared.u64 t, %1; cvt.u32.u64 %0, t; }"
        : "=r"(a) : "l"(p));
    return a;
}
__device__ __forceinline__ uint32_t sw128(uint32_t off) {
    return off ^ ((off >> 3) & 0x70);
}

#define CP_A16(d, s) \
    asm volatile("cp.async.cg.shared.global [%0], [%1], 16;" :: "r"(d), "l"(s) : "memory")
#define CP_COMMIT() asm volatile("cp.async.commit_group;" ::: "memory")
#define CP_WAIT1()  asm volatile("cp.async.wait_group 1;" ::: "memory")
#define CP_WAIT0()  asm volatile("cp.async.wait_group 0;" ::: "memory")
#define LDSM4(r, addr) \
    asm volatile("ldmatrix.sync.aligned.m8n8.x4.shared.b16 {%0,%1,%2,%3}, [%4];" \
        : "=r"((r)[0]), "=r"((r)[1]), "=r"((r)[2]), "=r"((r)[3]) : "r"(addr))
#define MMA_F16(d, a0, a1, a2, a3, b0, b1) \
    asm volatile("mma.sync.aligned.m16n8k16.row.col.f32.f16.f16.f32 " \
        "{%0,%1,%2,%3}, {%4,%5,%6,%7}, {%8,%9}, {%0,%1,%2,%3};" \
        : "+f"((d)[0]), "+f"((d)[1]), "+f"((d)[2]), "+f"((d)[3]) \
        : "r"(a0), "r"(a1), "r"(a2), "r"(a3), "r"(b0), "r"(b1))

__device__ __forceinline__ void store2(float* p, float x, float y) {
    *(float2*)p = make_float2(x, y);
}
__device__ __forceinline__ void store2(__half* p, float x, float y) {
    *(__half2*)p = __floats2half2_rn(x, y);
}

// ---------------------------------------------------------------------------
__global__ void cvt_both_kernel(const float* __restrict__ p, const float* __restrict__ l,
                                __half* __restrict__ ph, __half* __restrict__ lh,
                                int np4, int ntot4)
{
    int i = blockIdx.x * blockDim.x + threadIdx.x;
    if (i >= ntot4) return;
    const float* in;
    __half* out;
    int j;
    if (i < np4) { in = p; out = ph; j = i; }
    else         { in = l; out = lh; j = i - np4; }
    float4 v = reinterpret_cast<const float4*>(in)[j];
    reinterpret_cast<__half2*>(out)[2 * j]     = __floats2half2_rn(v.x, v.y);
    reinterpret_cast<__half2*>(out)[2 * j + 1] = __floats2half2_rn(v.z, v.w);
}

__global__ void transpose_all_kernel(const float* __restrict__ Wq, const float* __restrict__ Wk,
                                     const float* __restrict__ Wv, const float* __restrict__ Wo,
                                     __half* __restrict__ WtQ, __half* __restrict__ WtKV,
                                     __half* __restrict__ WtO)
{
    __shared__ float t[32][33];
    int z = blockIdx.z;
    const float* W;
    __half* Wt;
    int N, nb, rowoff = 0;
    if (z == 0)      { W = Wq; Wt = WtQ; N = D_; nb = blockIdx.x * 32; }
    else if (z == 1) { W = Wo; Wt = WtO; N = D_; nb = blockIdx.x * 32; }
    else {
        if (blockIdx.x >= 16) return;
        if (blockIdx.x < 8) { W = Wk; rowoff = 0;   nb = blockIdx.x * 32; }
        else                { W = Wv; rowoff = 256; nb = (blockIdx.x - 8) * 32; }
        Wt = WtKV; N = KVH_ * HD_;
    }
    int kb = blockIdx.y * 32;
    int x = threadIdx.x, y = threadIdx.y;
#pragma unroll
    for (int i = 0; i < 32; i += 8)
        t[y + i][x] = W[(size_t)(kb + y + i) * N + nb + x];
    __syncthreads();
#pragma unroll
    for (int i = 0; i < 32; i += 8)
        Wt[(size_t)(rowoff + nb + y + i) * D_ + kb + x] = __float2half_rn(t[x][y + i]);
}

__global__ void rope_table_kernel(const int* __restrict__ nf_ptr,
                                  const float* __restrict__ bk, const float* __restrict__ bv)
{
    if (blockIdx.x == 0) g_bkv[threadIdx.x] = bk[threadIdx.x];
    if (blockIdx.x == 1) g_bkv[256 + threadIdx.x] = bv[threadIdx.x];
    int nf = *nf_ptr;
    if (nf <= 1 || nf > NF_MAX) return;
    int idx = blockIdx.x * blockDim.x + threadIdx.x;
    if (idx >= nf * 32) return;
    int j = idx & 31, pos = idx >> 5;
    float inv = powf(10000.0f, -(float)(2 * j) / 64.0f);
    float th = (float)pos * inv;
    g_rope[idx] = cosf(th);
    g_rope[NF_MAX * 32 + idx] = sinf(th);
}

// ---------------------------------------------------------------------------
// fp16 mma.sync GEMM: C = A @ Bt^T + bias. CTA 128x128, 8 warps (64x32),
// BK=64 halves, 3-stage cp.async, ONE __syncthreads per iteration.
// ---------------------------------------------------------------------------
#define GSTAGE 32768u
#define GEMM_SMEM (3 * 32768)

__device__ __forceinline__ void load_tile(const __half* Ag, const __half* Bg, int K,
                                          uint32_t buf, int tid)
{
    uint32_t aBuf = buf, bBuf = buf + 16384u;
#pragma unroll
    for (int j = 0; j < 4; j++) {
        int idx = j * 256 + tid;
        int row = idx >> 3, k8 = idx & 7;
        uint32_t off = sw128((uint32_t)(row * 128 + k8 * 16));
        CP_A16(aBuf + off, Ag + (size_t)row * K + k8 * 8);
        CP_A16(bBuf + off, Bg + (size_t)row * K + k8 * 8);
    }
}

template <typename OutT>
__global__ __launch_bounds__(256)
void gemm_f16(const __half* __restrict__ A, const __half* __restrict__ Bt,
              const float* __restrict__ bias, OutT* __restrict__ C,
              int M, int N, int K)
{
    extern __shared__ char smraw[];
    uint32_t data = smem_u32(smraw);   // dynamic smem is sufficiently aligned

    int tid = threadIdx.x, lane = tid & 31, wid = tid >> 5;
    int wm = (wid >> 2) * 64;
    int wn = (wid & 3) * 32;

    const __half* Ag = A  + (size_t)blockIdx.y * 128 * K;
    const __half* Bg = Bt + (size_t)blockIdx.x * 128 * K;

    float acc[4][4][4];
#pragma unroll
    for (int i = 0; i < 4; i++)
#pragma unroll
        for (int j = 0; j < 4; j++)
#pragma unroll
            for (int k = 0; k < 4; k++) acc[i][j][k] = 0.f;

    int T = K >> 6;

    // prologue: stages 0 and 1
    load_tile(Ag, Bg, K, data, tid);
    CP_COMMIT();
    if (T > 1) load_tile(Ag + 64, Bg + 64, K, data + GSTAGE, tid);
    CP_COMMIT();

    int lmat = lane >> 3, lrow = lane & 7;
    int frow = ((lmat & 2) ? 8 : 0) + lrow;
    int fcol = (lmat & 1) * 16;

    int stage = 0;
    for (int t = 0; t < T; ++t) {
        CP_WAIT1();          // stage t resident
        __syncthreads();     // visible to all; also frees stage (t+2)%3

        if (t + 2 < T)
            load_tile(Ag + (t + 2) * 64, Bg + (t + 2) * 64, K,
                      data + (uint32_t)((stage + 2) % 3) * GSTAGE, tid);
        CP_COMMIT();

        uint32_t aB = data + (uint32_t)stage * GSTAGE;
        uint32_t bB = aB + 16384u;
#pragma unroll
        for (int kk = 0; kk < 4; ++kk) {
            uint32_t af[4][4], bf[2][4];
#pragma unroll
            for (int mi = 0; mi < 4; ++mi) {
                uint32_t addr = aB + sw128((uint32_t)((wm + mi * 16 + frow) * 128 + kk * 32 + fcol));
                LDSM4(af[mi], addr);
            }
#pragma unroll
            for (int nj = 0; nj < 2; ++nj) {
                uint32_t addr = bB + sw128((uint32_t)((wn + nj * 16 + frow) * 128 + kk * 32 + fcol));
                LDSM4(bf[nj], addr);
            }
#pragma unroll
            for (int mi = 0; mi < 4; ++mi)
#pragma unroll
                for (int ni = 0; ni < 4; ++ni) {
                    int nj = ni >> 1, lh = (ni & 1) * 2;
                    MMA_F16(acc[mi][ni],
                            af[mi][0], af[mi][2], af[mi][1], af[mi][3],
                            bf[nj][lh], bf[nj][lh + 1]);
                }
        }
        stage = (stage + 1) % 3;
    }

    int rbase = blockIdx.y * 128 + wm + (lane >> 2);
    int cbase = blockIdx.x * 128 + wn + (lane & 3) * 2;
#pragma unroll
    for (int mi = 0; mi < 4; ++mi) {
#pragma unroll
        for (int ni = 0; ni < 4; ++ni) {
            int c = cbase + ni * 8;
            float2 bv = *(const float2*)(bias + c);
            int r0 = rbase + mi * 16;
            store2(C + (size_t)r0 * N + c, acc[mi][ni][0] + bv.x, acc[mi][ni][1] + bv.y);
            store2(C + (size_t)(r0 + 8) * N + c, acc[mi][ni][2] + bv.x, acc[mi][ni][3] + bv.y);
        }
    }
}

// ---------------------------------------------------------------------------
// fp16 MMA flash attention with fused RoPE (unchanged from round 9).
// ---------------------------------------------------------------------------
#define QS_OFF 0u
#define KS_OFF 16384u
#define VT_OFF 49152u
#define PS_OFF 81920u
#define ATTN_SMEM 114688

__global__ __launch_bounds__(256)
void attn_kernel(const __half* __restrict__ Q, const __half* __restrict__ KV,
                 __half* __restrict__ O, const int* __restrict__ nf_ptr)
{
    extern __shared__ char sm[];
    uint32_t smb = smem_u32(sm);

    int tid = threadIdx.x, l = tid & 31, w = tid >> 5;
    int b = blockIdx.z, h = blockIdx.y, qt = blockIdx.x;
    int kvh = h >> 2;
    int nf = *nf_ptr;
    bool rope = (nf > 1) && (nf <= NF_MAX);
    int qdiv = rope ? (LQ_ / nf) : 1;
    int kdiv = rope ? (LKV_ / nf) : 1;

    {
        int row = tid >> 1, part = tid & 1;
        int qglob = qt * 128 + row;
        const __half* src = Q + ((size_t)(b * LQ_ + qglob)) * D_ + h * HD_;
        int pos = rope ? (qglob / qdiv) : 0;
        const float* ct = g_rope + pos * 32;
        const float* st = g_rope + NF_MAX * 32 + pos * 32;
#pragma unroll
        for (int jj = 0; jj < 4; jj++) {
            int j = part * 16 + jj * 4;
            __half2 u0 = *(const __half2*)(src + j);
            __half2 u1 = *(const __half2*)(src + j + 2);
            __half2 v0 = *(const __half2*)(src + j + 32);
            __half2 v1 = *(const __half2*)(src + j + 34);
            float a1[4] = { __low2float(u0), __high2float(u0), __low2float(u1), __high2float(u1) };
            float a2[4] = { __low2float(v0), __high2float(v0), __low2float(v1), __high2float(v1) };
            float y1[4], y2[4];
#pragma unroll
            for (int e = 0; e < 4; e++) {
                float c = 1.f, s = 0.f;
                if (rope) { c = ct[j + e], s = st[j + e]; }
                y1[e] = (a1[e] * c - a2[e] * s) * 0.125f;
                y2[e] = (a2[e] * c + a1[e] * s) * 0.125f;
            }
            uint32_t o0 = QS_OFF + sw128((uint32_t)(row * 128 + j * 2));
            uint32_t o1 = QS_OFF + sw128((uint32_t)(row * 128 + (j + 32) * 2));
            ((__half2*)(sm + o0))[0] = __floats2half2_rn(y1[0], y1[1]);
            ((__half2*)(sm + o0))[1] = __floats2half2_rn(y1[2], y1[3]);
            ((__half2*)(sm + o1))[0] = __floats2half2_rn(y2[0], y2[1]);
            ((__half2*)(sm + o1))[1] = __floats2half2_rn(y2[2], y2[3]);
        }
    }

#pragma unroll
    for (int u = tid; u < 512; u += 256) {
        int row = u >> 1, part = u & 1;
        const __half* src = KV + (size_t)(b * LKV_ + row) * 512 + kvh * HD_;
        int pos = rope ? (row / kdiv) : 0;
        const float* ct = g_rope + pos * 32;
        const float* st = g_rope + NF_MAX * 32 + pos * 32;
#pragma unroll
        for (int jj = 0; jj < 4; jj++) {
            int j = part * 16 + jj * 4;
            __half2 u0 = *(const __half2*)(src + j);
            __half2 u1 = *(const __half2*)(src + j + 2);
            __half2 v0 = *(const __half2*)(src + j + 32);
            __half2 v1 = *(const __half2*)(src + j + 34);
            float a1[4] = { __low2float(u0), __high2float(u0), __low2float(u1), __high2float(u1) };
            float a2[4] = { __low2float(v0), __high2float(v0), __low2float(v1), __high2float(v1) };
            float y1[4], y2[4];
#pragma unroll
            for (int e = 0; e < 4; e++) {
                float c = 1.f, s = 0.f;
                if (rope) { c = ct[j + e], s = st[j + e]; }
                y1[e] = a1[e] * c - a2[e] * s;
                y2[e] = a2[e] * c + a1[e] * s;
            }
            uint32_t o0 = KS_OFF + sw128((uint32_t)(row * 128 + j * 2));
            uint32_t o1 = KS_OFF + sw128((uint32_t)(row * 128 + (j + 32) * 2));
            ((__half2*)(sm + o0))[0] = __floats2half2_rn(y1[0], y1[1]);
            ((__half2*)(sm + o0))[1] = __floats2half2_rn(y1[2], y1[3]);
            ((__half2*)(sm + o1))[0] = __floats2half2_rn(y2[0], y2[1]);
            ((__half2*)(sm + o1))[1] = __floats2half2_rn(y2[2], y2[3]);
        }
    }

#pragma unroll
    for (int it = 0; it < 8; it++) {
        int idx = it * 256 + tid;
        int kv = idx >> 3, c8 = idx & 7;
        const __half* src = KV + (size_t)(b * LKV_ + kv) * 512 + 256 + kvh * HD_ + c8 * 8;
        uint4 raw = *(const uint4*)src;
        const __half* hv = (const __half*)&raw;
        uint32_t base = VT_OFF + (uint32_t)(kv >> 6) * 8192u;
        int kcol = (kv & 63) * 2;
#pragma unroll
        for (int e = 0; e < 8; e++) {
            int d = c8 * 8 + e;
            *(__half*)(sm + base + sw128((uint32_t)(d * 128 + kcol))) = hv[e];
        }
    }
    __syncthreads();

    int lmat = l >> 3, lrow = l & 7;
    int frow = ((lmat & 2) ? 8 : 0) + lrow;
    int fcol = (lmat & 1) * 16;
    int mrow = w * 16 + frow;

    uint32_t qf[4][4];
#pragma unroll
    for (int kk = 0; kk < 4; kk++) {
        uint32_t a = smb + QS_OFF + sw128((uint32_t)(mrow * 128 + kk * 32 + fcol));
        LDSM4(qf[kk], a);
    }

    float oacc[8][4];
#pragma unroll
    for (int i = 0; i < 8; i++)
#pragma unroll
        for (int j = 0; j < 4; j++) oacc[i][j] = 0.f;
    float rs0 = 0.f, rs1 = 0.f;

#pragma unroll
    for (int c = 0; c < 2; c++) {
        float sc[16][4];
#pragma unroll
        for (int i = 0; i < 16; i++)
#pragma unroll
            for (int j = 0; j < 4; j++) sc[i][j] = 0.f;

#pragma unroll
        for (int ng = 0; ng < 8; ng++) {
            int kvrow = c * 128 + ng * 16 + frow;
#pragma unroll
            for (int kk = 0; kk < 4; kk++) {
                uint32_t bf[4];
                uint32_t a = smb + KS_OFF + sw128((uint32_t)(kvrow * 128 + kk * 32 + fcol));
                LDSM4(bf, a);
                MMA_F16(sc[2 * ng],     qf[kk][0], qf[kk][2], qf[kk][1], qf[kk][3], bf[0], bf[1]);
                MMA_F16(sc[2 * ng + 1], qf[kk][0], qf[kk][2], qf[kk][1], qf[kk][3], bf[2], bf[3]);
            }
        }

        int r0 = w * 16 + (l >> 2);
#pragma unroll
        for (int nt = 0; nt < 16; nt++) {
            float p0 = __expf(sc[nt][0]);
            float p1 = __expf(sc[nt][1]);
            float p2 = __expf(sc[nt][2]);
            float p3 = __expf(sc[nt][3]);
            rs0 += p0 + p1;
            rs1 += p2 + p3;
            int kvl = nt * 8 + 2 * (l & 3);
            uint32_t bo = PS_OFF + (uint32_t)(kvl >> 6) * 16384u;
            int kc = (kvl & 63) * 2;
            *(__half2*)(sm + bo + sw128((uint32_t)(r0 * 128 + kc)))
                = __floats2half2_rn(p0, p1);
            *(__half2*)(sm + bo + sw128((uint32_t)((r0 + 8) * 128 + kc)))
                = __floats2half2_rn(p2, p3);
        }
        __syncwarp();

        uint32_t pf[8][4];
#pragma unroll
        for (int kt = 0; kt < 8; kt++) {
            uint32_t a = smb + PS_OFF + (uint32_t)(kt >> 2) * 16384u
                       + sw128((uint32_t)(mrow * 128 + (kt & 3) * 32 + fcol));
            LDSM4(pf[kt], a);
        }
#pragma unroll
        for (int dg = 0; dg < 4; dg++) {
#pragma unroll
            for (int kt = 0; kt < 8; kt++) {
                uint32_t bf[4];
                uint32_t a = smb + VT_OFF + (uint32_t)(2 * c + (kt >> 2)) * 8192u
                           + sw128((uint32_t)((dg * 16 + frow) * 128 + (kt & 3) * 32 + fcol));
                LDSM4(bf, a);
                MMA_F16(oacc[2 * dg],     pf[kt][0], pf[kt][2], pf[kt][1], pf[kt][3], bf[0], bf[1]);
                MMA_F16(oacc[2 * dg + 1], pf[kt][0], pf[kt][2], pf[kt][1], pf[kt][3], bf[2], bf[3]);
            }
        }
        __syncwarp();
    }

    rs0 += __shfl_xor_sync(0xFFFFFFFFu, rs0, 1);
    rs0 += __shfl_xor_sync(0xFFFFFFFFu, rs0, 2);
    rs1 += __shfl_xor_sync(0xFFFFFFFFu, rs1, 1);
    rs1 += __shfl_xor_sync(0xFFFFFFFFu, rs1, 2);
    float inv0 = 1.0f / rs0, inv1 = 1.0f / rs1;

    int q0 = qt * 128 + w * 16 + (l >> 2);
    __half* o0 = O + ((size_t)(b * LQ_ + q0)) * D_ + h * HD_;
    __half* o1 = o0 + 8 * D_;
#pragma unroll
    for (int nt = 0; nt < 8; nt++) {
        int dcol = nt * 8 + 2 * (l & 3);
        *(__half2*)(o0 + dcol) = __floats2half2_rn(oacc[nt][0] * inv0, oacc[nt][1] * inv0);
        *(__half2*)(o1 + dcol) = __floats2half2_rn(oacc[nt][2] * inv1, oacc[nt][3] * inv1);
    }
}

// ---------------------------------------------------------------------------
extern "C" void kernel_launch(void* const* d_in, const int* in_sizes, int n_in,
                              void* d_out, int out_size)
{
    const float* patches = (const float*)d_in[0];
    const float* latents = (const float*)d_in[1];
    const float* Wq = (const float*)d_in[2];
    const float* bq = (const float*)d_in[3];
    const float* Wk = (const float*)d_in[4];
    const float* bk = (const float*)d_in[5];
    const float* Wv = (const float*)d_in[6];
    const float* bv = (const float*)d_in[7];
    const float* Wo = (const float*)d_in[8];
    const float* bo = (const float*)d_in[9];
    const int*   nf = (const int*)d_in[10];
    float* out = (float*)d_out;

    __half *Ph, *Lh, *Qd, *KVd, *Ad, *WtQ, *WtKV, *WtO;
    float *bkv;
    cudaGetSymbolAddress((void**)&Ph,   g_Ph);
    cudaGetSymbolAddress((void**)&Lh,   g_Lh);
    cudaGetSymbolAddress((void**)&Qd,   g_Q);
    cudaGetSymbolAddress((void**)&KVd,  g_KV);
    cudaGetSymbolAddress((void**)&Ad,   g_attn);
    cudaGetSymbolAddress((void**)&WtQ,  g_WtQ);
    cudaGetSymbolAddress((void**)&WtKV, g_WtKV);
    cudaGetSymbolAddress((void**)&WtO,  g_WtO);
    cudaGetSymbolAddress((void**)&bkv,  g_bkv);

    cudaFuncSetAttribute(gemm_f16<__half>, cudaFuncAttributeMaxDynamicSharedMemorySize, GEMM_SMEM);
    cudaFuncSetAttribute(gemm_f16<float>,  cudaFuncAttributeMaxDynamicSharedMemorySize, GEMM_SMEM);
    cudaFuncSetAttribute(attn_kernel, cudaFuncAttributeMaxDynamicSharedMemorySize, ATTN_SMEM);

    // 0) prep (3 launches)
    transpose_all_kernel<<<dim3(32, 32, 3), dim3(32, 8)>>>(Wq, Wk, Wv, Wo, WtQ, WtKV, WtO);
    rope_table_kernel<<<(NF_MAX * 32) / 256, 256>>>(nf, bk, bv);
    int np4 = B_ * LQ_ * D_ / 4;
    int nl4 = B_ * LKV_ * D_ / 4;
    cvt_both_kernel<<<(np4 + nl4 + 255) / 256, 256>>>(patches, latents, Ph, Lh, np4, np4 + nl4);

    // 1) Q projection (half out)
    gemm_f16<__half><<<dim3(D_ / 128, (B_ * LQ_) / 128), 256, GEMM_SMEM>>>(
        Ph, WtQ, bq, Qd, B_ * LQ_, D_, D_);

    // 2) fused K|V projection (half out, N=512)
    gemm_f16<__half><<<dim3(512 / 128, (B_ * LKV_) / 128), 256, GEMM_SMEM>>>(
        Lh, WtKV, bkv, KVd, B_ * LKV_, 512, D_);

    // 3) attention (fp16 mma + fused RoPE)
    dim3 ga(LQ_ / 128, H_, B_);
    attn_kernel<<<ga, 256, ATTN_SMEM>>>(Qd, KVd, Ad, nf);

    // 4) output projection (float out)
    gemm_f16<float><<<dim3(D_ / 128, (B_ * LQ_) / 128), 256, GEMM_SMEM>>>(
        Ad, WtO, bo, out, B_ * LQ_, D_, D_);
}

// round 11
// speedup vs baseline: 1.1534x; 1.1534x over previous
#include <cuda_runtime.h>
#include <cuda_fp16.h>
#include <math.h>
#include <stdint.h>

#define B_    4
#define LQ_   4096
#define LKV_  256
#define D_    1024
#define H_    16
#define KVH_  4
#define HD_   64
#define NF_MAX 4096

// ---------------- scratch (device globals; no allocation allowed) ----------
__device__ __half g_Ph[(size_t)B_ * LQ_ * D_];          // fp16 patches
__device__ __half g_Lh[(size_t)B_ * LKV_ * D_];         // fp16 latents
__device__ __half g_Q[(size_t)B_ * LQ_ * D_];           // fp16 Q
__device__ __half g_KV[(size_t)B_ * LKV_ * 512];        // fused K|V
__device__ __half g_attn[(size_t)B_ * LQ_ * D_];        // fp16 attn out
__device__ __half g_WtQ[(size_t)D_ * D_];               // W^T [N][K] fp16
__device__ __half g_WtKV[(size_t)512 * D_];             // [Wk^T ; Wv^T]
__device__ __half g_WtO[(size_t)D_ * D_];
__device__ float  g_bkv[512];                            // bk | bv
__device__ float  g_rope[2 * NF_MAX * 32];              // cos | sin

// ---------------- helpers ---------------------------------------------------
__device__ __forceinline__ uint32_t smem_u32(const void* p) {
    uint32_t a;
    asm("{ .reg .u64 t; cvta.to.shared.u64 t, %1; cvt.u32.u64 %0, t; }"
        : "=r"(a) : "l"(p));
    return a;
}
__device__ __forceinline__ uint32_t sw128(uint32_t off) {
    return off ^ ((off >> 3) & 0x70);
}

#define CP_A16(d, s) \
    asm volatile("cp.async.cg.shared.global [%0], [%1], 16;" :: "r"(d), "l"(s) : "memory")
#define CP_COMMIT() asm volatile("cp.async.commit_group;" ::: "memory")
#define CP_WAIT1()  asm volatile("cp.async.wait_group 1;" ::: "memory")
#define CP_WAIT0()  asm volatile("cp.async.wait_group 0;" ::: "memory")
#define LDSM4(r, addr) \
    asm volatile("ldmatrix.sync.aligned.m8n8.x4.shared.b16 {%0,%1,%2,%3}, [%4];" \
        : "=r"((r)[0]), "=r"((r)[1]), "=r"((r)[2]), "=r"((r)[3]) : "r"(addr))
#define MMA_F16(d, a0, a1, a2, a3, b0, b1) \
    asm volatile("mma.sync.aligned.m16n8k16.row.col.f32.f16.f16.f32 " \
        "{%0,%1,%2,%3}, {%4,%5,%6,%7}, {%8,%9}, {%0,%1,%2,%3};" \
        : "+f"((d)[0]), "+f"((d)[1]), "+f"((d)[2]), "+f"((d)[3]) \
        : "r"(a0), "r"(a1), "r"(a2), "r"(a3), "r"(b0), "r"(b1))

__device__ __forceinline__ void store2(float* p, float x, float y) {
    *(float2*)p = make_float2(x, y);
}
__device__ __forceinline__ void store2(__half* p, float x, float y) {
    *(__half2*)p = __floats2half2_rn(x, y);
}

// ---------------------------------------------------------------------------
__global__ void cvt_both_kernel(const float* __restrict__ p, const float* __restrict__ l,
                                __half* __restrict__ ph, __half* __restrict__ lh,
                                int np4, int ntot4)
{
    int i = blockIdx.x * blockDim.x + threadIdx.x;
    if (i >= ntot4) return;
    const float* in;
    __half* out;
    int j;
    if (i < np4) { in = p; out = ph; j = i; }
    else         { in = l; out = lh; j = i - np4; }
    float4 v = reinterpret_cast<const float4*>(in)[j];
    reinterpret_cast<__half2*>(out)[2 * j]     = __floats2half2_rn(v.x, v.y);
    reinterpret_cast<__half2*>(out)[2 * j + 1] = __floats2half2_rn(v.z, v.w);
}

__global__ void transpose_all_kernel(const float* __restrict__ Wq, const float* __restrict__ Wk,
                                     const float* __restrict__ Wv, const float* __restrict__ Wo,
                                     __half* __restrict__ WtQ, __half* __restrict__ WtKV,
                                     __half* __restrict__ WtO)
{
    __shared__ float t[32][33];
    int z = blockIdx.z;
    const float* W;
    __half* Wt;
    int N, nb, rowoff = 0;
    if (z == 0)      { W = Wq; Wt = WtQ; N = D_; nb = blockIdx.x * 32; }
    else if (z == 1) { W = Wo; Wt = WtO; N = D_; nb = blockIdx.x * 32; }
    else {
        if (blockIdx.x >= 16) return;
        if (blockIdx.x < 8) { W = Wk; rowoff = 0;   nb = blockIdx.x * 32; }
        else                { W = Wv; rowoff = 256; nb = (blockIdx.x - 8) * 32; }
        Wt = WtKV; N = KVH_ * HD_;
    }
    int kb = blockIdx.y * 32;
    int x = threadIdx.x, y = threadIdx.y;
#pragma unroll
    for (int i = 0; i < 32; i += 8)
        t[y + i][x] = W[(size_t)(kb + y + i) * N + nb + x];
    __syncthreads();
#pragma unroll
    for (int i = 0; i < 32; i += 8)
        Wt[(size_t)(rowoff + nb + y + i) * D_ + kb + x] = __float2half_rn(t[x][y + i]);
}

__global__ void rope_table_kernel(const int* __restrict__ nf_ptr,
                                  const float* __restrict__ bk, const float* __restrict__ bv)
{
    if (blockIdx.x == 0) g_bkv[threadIdx.x] = bk[threadIdx.x];
    if (blockIdx.x == 1) g_bkv[256 + threadIdx.x] = bv[threadIdx.x];
    int nf = *nf_ptr;
    if (nf <= 1 || nf > NF_MAX) return;
    int idx = blockIdx.x * blockDim.x + threadIdx.x;
    if (idx >= nf * 32) return;
    int j = idx & 31, pos = idx >> 5;
    float inv = powf(10000.0f, -(float)(2 * j) / 64.0f);
    float th = (float)pos * inv;
    g_rope[idx] = cosf(th);
    g_rope[NF_MAX * 32 + idx] = sinf(th);
}

// ---------------------------------------------------------------------------
// fp16 mma.sync GEMM (EXACT round-9 proven version): C = A @ Bt^T + bias
// CTA 128x128, 256 thr (8 warps, 64x32), BK=64 halves, 2-stage cp.async.
// 128 regs -> 2 CTAs/SM. DO NOT restructure (R5/R6/R10 all regressed).
// ---------------------------------------------------------------------------
#define GEMM_SMEM (1024 + 4 * 16384)

__device__ __forceinline__ void load_tile(const __half* Ag, const __half* Bg, int K,
                                          uint32_t aBuf, uint32_t bBuf, int tid)
{
#pragma unroll
    for (int j = 0; j < 4; j++) {
        int idx = j * 256 + tid;
        int row = idx >> 3, k8 = idx & 7;
        uint32_t off = sw128((uint32_t)(row * 128 + k8 * 16));
        CP_A16(aBuf + off, Ag + (size_t)row * K + k8 * 8);
        CP_A16(bBuf + off, Bg + (size_t)row * K + k8 * 8);
    }
}

template <typename OutT>
__global__ __launch_bounds__(256)
void gemm_f16(const __half* __restrict__ A, const __half* __restrict__ Bt,
              const float* __restrict__ bias, OutT* __restrict__ C,
              int M, int N, int K)
{
    extern __shared__ char smraw[];
    uint32_t base = smem_u32(smraw);
    uint32_t data = (base + 1023u) & ~1023u;

    int tid = threadIdx.x, lane = tid & 31, wid = tid >> 5;
    int wm = (wid >> 2) * 64;
    int wn = (wid & 3) * 32;

    const __half* Ag = A  + (size_t)blockIdx.y * 128 * K;
    const __half* Bg = Bt + (size_t)blockIdx.x * 128 * K;

    float acc[4][4][4];
#pragma unroll
    for (int i = 0; i < 4; i++)
#pragma unroll
        for (int j = 0; j < 4; j++)
#pragma unroll
            for (int k = 0; k < 4; k++) acc[i][j][k] = 0.f;

    int T = K >> 6;
    load_tile(Ag, Bg, K, data, data + 16384u, tid);
    CP_COMMIT();

    int lmat = lane >> 3, lrow = lane & 7;
    int frow = ((lmat & 2) ? 8 : 0) + lrow;
    int fcol = (lmat & 1) * 16;

    for (int t = 0; t < T; ++t) {
        int st = t & 1;
        if (t + 1 < T) {
            uint32_t nb = data + (uint32_t)((t + 1) & 1) * 32768u;
            load_tile(Ag + (t + 1) * 64, Bg + (t + 1) * 64, K, nb, nb + 16384u, tid);
            CP_COMMIT();
            CP_WAIT1();
        } else {
            CP_WAIT0();
        }
        __syncthreads();

        uint32_t aB = data + (uint32_t)st * 32768u;
        uint32_t bB = aB + 16384u;
#pragma unroll
        for (int kk = 0; kk < 4; ++kk) {
            uint32_t af[4][4], bf[2][4];
#pragma unroll
            for (int mi = 0; mi < 4; ++mi) {
                uint32_t addr = aB + sw128((uint32_t)((wm + mi * 16 + frow) * 128 + kk * 32 + fcol));
                LDSM4(af[mi], addr);
            }
#pragma unroll
            for (int nj = 0; nj < 2; ++nj) {
                uint32_t addr = bB + sw128((uint32_t)((wn + nj * 16 + frow) * 128 + kk * 32 + fcol));
                LDSM4(bf[nj], addr);
            }
#pragma unroll
            for (int mi = 0; mi < 4; ++mi)
#pragma unroll
                for (int ni = 0; ni < 4; ++ni) {
                    int nj = ni >> 1, lh = (ni & 1) * 2;
                    MMA_F16(acc[mi][ni],
                            af[mi][0], af[mi][2], af[mi][1], af[mi][3],
                            bf[nj][lh], bf[nj][lh + 1]);
                }
        }
        __syncthreads();
    }

    int rbase = blockIdx.y * 128 + wm + (lane >> 2);
    int cbase = blockIdx.x * 128 + wn + (lane & 3) * 2;
#pragma unroll
    for (int mi = 0; mi < 4; ++mi) {
#pragma unroll
        for (int ni = 0; ni < 4; ++ni) {
            int c = cbase + ni * 8;
            float2 bv = *(const float2*)(bias + c);
            int r0 = rbase + mi * 16;
            store2(C + (size_t)r0 * N + c, acc[mi][ni][0] + bv.x, acc[mi][ni][1] + bv.y);
            store2(C + (size_t)(r0 + 8) * N + c, acc[mi][ni][2] + bv.x, acc[mi][ni][3] + bv.y);
        }
    }
}

// ---------------------------------------------------------------------------
// fp16 MMA flash attention, fused RoPE. grid (LQ/128, H, B), 256 threads.
// SMEM 96KB (2 CTAs/SM):
//   QS/PS0 0     : [128][64] 16KB  Q tile; REUSED as P sub0 after qf load
//                  (per-warp safe: warp w only touches rows [16w,16w+16))
//   KS 16384     : [256][64] 32KB
//   VT 49152     : 4 x [64][64] 32KB (V^T)
//   PS1 81920    : [128][64] 16KB  P sub1
// ---------------------------------------------------------------------------
#define QS_OFF 0u
#define KS_OFF 16384u
#define VT_OFF 49152u
#define PS1_OFF 81920u
#define ATTN_SMEM 98304

__global__ __launch_bounds__(256)
void attn_kernel(const __half* __restrict__ Q, const __half* __restrict__ KV,
                 __half* __restrict__ O, const int* __restrict__ nf_ptr)
{
    extern __shared__ char sm[];
    uint32_t smb = smem_u32(sm);

    int tid = threadIdx.x, l = tid & 31, w = tid >> 5;
    int b = blockIdx.z, h = blockIdx.y, qt = blockIdx.x;
    int kvh = h >> 2;
    int nf = *nf_ptr;
    bool rope = (nf > 1) && (nf <= NF_MAX);
    int qdiv = rope ? (LQ_ / nf) : 1;
    int kdiv = rope ? (LKV_ / nf) : 1;

    // ---- Q tile: rope + scale ----------------------------------------------
    {
        int row = tid >> 1, part = tid & 1;
        int qglob = qt * 128 + row;
        const __half* src = Q + ((size_t)(b * LQ_ + qglob)) * D_ + h * HD_;
        int pos = rope ? (qglob / qdiv) : 0;
        const float* ct = g_rope + pos * 32;
        const float* st = g_rope + NF_MAX * 32 + pos * 32;
#pragma unroll
        for (int jj = 0; jj < 4; jj++) {
            int j = part * 16 + jj * 4;
            __half2 u0 = *(const __half2*)(src + j);
            __half2 u1 = *(const __half2*)(src + j + 2);
            __half2 v0 = *(const __half2*)(src + j + 32);
            __half2 v1 = *(const __half2*)(src + j + 34);
            float a1[4] = { __low2float(u0), __high2float(u0), __low2float(u1), __high2float(u1) };
            float a2[4] = { __low2float(v0), __high2float(v0), __low2float(v1), __high2float(v1) };
            float y1[4], y2[4];
#pragma unroll
            for (int e = 0; e < 4; e++) {
                float c = 1.f, s = 0.f;
                if (rope) { c = ct[j + e], s = st[j + e]; }
                y1[e] = (a1[e] * c - a2[e] * s) * 0.125f;
                y2[e] = (a2[e] * c + a1[e] * s) * 0.125f;
            }
            uint32_t o0 = QS_OFF + sw128((uint32_t)(row * 128 + j * 2));
            uint32_t o1 = QS_OFF + sw128((uint32_t)(row * 128 + (j + 32) * 2));
            ((__half2*)(sm + o0))[0] = __floats2half2_rn(y1[0], y1[1]);
            ((__half2*)(sm + o0))[1] = __floats2half2_rn(y1[2], y1[3]);
            ((__half2*)(sm + o1))[0] = __floats2half2_rn(y2[0], y2[1]);
            ((__half2*)(sm + o1))[1] = __floats2half2_rn(y2[2], y2[3]);
        }
    }

    // ---- K tile: rope -------------------------------------------------------
#pragma unroll
    for (int u = tid; u < 512; u += 256) {
        int row = u >> 1, part = u & 1;
        const __half* src = KV + (size_t)(b * LKV_ + row) * 512 + kvh * HD_;
        int pos = rope ? (row / kdiv) : 0;
        const float* ct = g_rope + pos * 32;
        const float* st = g_rope + NF_MAX * 32 + pos * 32;
#pragma unroll
        for (int jj = 0; jj < 4; jj++) {
            int j = part * 16 + jj * 4;
            __half2 u0 = *(const __half2*)(src + j);
            __half2 u1 = *(const __half2*)(src + j + 2);
            __half2 v0 = *(const __half2*)(src + j + 32);
            __half2 v1 = *(const __half2*)(src + j + 34);
            float a1[4] = { __low2float(u0), __high2float(u0), __low2float(u1), __high2float(u1) };
            float a2[4] = { __low2float(v0), __high2float(v0), __low2float(v1), __high2float(v1) };
            float y1[4], y2[4];
#pragma unroll
            for (int e = 0; e < 4; e++) {
                float c = 1.f, s = 0.f;
                if (rope) { c = ct[j + e], s = st[j + e]; }
                y1[e] = a1[e] * c - a2[e] * s;
                y2[e] = a2[e] * c + a1[e] * s;
            }
            uint32_t o0 = KS_OFF + sw128((uint32_t)(row * 128 + j * 2));
            uint32_t o1 = KS_OFF + sw128((uint32_t)(row * 128 + (j + 32) * 2));
            ((__half2*)(sm + o0))[0] = __floats2half2_rn(y1[0], y1[1]);
            ((__half2*)(sm + o0))[1] = __floats2half2_rn(y1[2], y1[3]);
            ((__half2*)(sm + o1))[0] = __floats2half2_rn(y2[0], y2[1]);
            ((__half2*)(sm + o1))[1] = __floats2half2_rn(y2[2], y2[3]);
        }
    }

    // ---- V transposed -------------------------------------------------------
#pragma unroll
    for (int it = 0; it < 8; it++) {
        int idx = it * 256 + tid;
        int kv = idx >> 3, c8 = idx & 7;
        const __half* src = KV + (size_t)(b * LKV_ + kv) * 512 + 256 + kvh * HD_ + c8 * 8;
        uint4 raw = *(const uint4*)src;
        const __half* hv = (const __half*)&raw;
        uint32_t base = VT_OFF + (uint32_t)(kv >> 6) * 8192u;
        int kcol = (kv & 63) * 2;
#pragma unroll
        for (int e = 0; e < 8; e++) {
            int d = c8 * 8 + e;
            *(__half*)(sm + base + sw128((uint32_t)(d * 128 + kcol))) = hv[e];
        }
    }
    __syncthreads();

    // ---- compute ------------------------------------------------------------
    int lmat = l >> 3, lrow = l & 7;
    int frow = ((lmat & 2) ? 8 : 0) + lrow;
    int fcol = (lmat & 1) * 16;
    int mrow = w * 16 + frow;

    uint32_t qf[4][4];
#pragma unroll
    for (int kk = 0; kk < 4; kk++) {
        uint32_t a = smb + QS_OFF + sw128((uint32_t)(mrow * 128 + kk * 32 + fcol));
        LDSM4(qf[kk], a);
    }
    __syncwarp();   // all lanes of this warp hold qf before QS rows are reused as P

    float oacc[8][4];
#pragma unroll
    for (int i = 0; i < 8; i++)
#pragma unroll
        for (int j = 0; j < 4; j++) oacc[i][j] = 0.f;
    float rs0 = 0.f, rs1 = 0.f;

#pragma unroll
    for (int c = 0; c < 2; c++) {
        float sc[16][4];
#pragma unroll
        for (int i = 0; i < 16; i++)
#pragma unroll
            for (int j = 0; j < 4; j++) sc[i][j] = 0.f;

#pragma unroll
        for (int ng = 0; ng < 8; ng++) {
            int kvrow = c * 128 + ng * 16 + frow;
#pragma unroll
            for (int kk = 0; kk < 4; kk++) {
                uint32_t bf[4];
                uint32_t a = smb + KS_OFF + sw128((uint32_t)(kvrow * 128 + kk * 32 + fcol));
                LDSM4(bf, a);
                MMA_F16(sc[2 * ng],     qf[kk][0], qf[kk][2], qf[kk][1], qf[kk][3], bf[0], bf[1]);
                MMA_F16(sc[2 * ng + 1], qf[kk][0], qf[kk][2], qf[kk][1], qf[kk][3], bf[2], bf[3]);
            }
        }

        int r0 = w * 16 + (l >> 2);
#pragma unroll
        for (int nt = 0; nt < 16; nt++) {
            float p0 = __expf(sc[nt][0]);
            float p1 = __expf(sc[nt][1]);
            float p2 = __expf(sc[nt][2]);
            float p3 = __expf(sc[nt][3]);
            rs0 += p0 + p1;
            rs1 += p2 + p3;
            int kvl = nt * 8 + 2 * (l & 3);
            uint32_t bo = (kvl & 64) ? PS1_OFF : QS_OFF;   // P sub0 aliases QS
            int kc = (kvl & 63) * 2;
            *(__half2*)(sm + bo + sw128((uint32_t)(r0 * 128 + kc)))
                = __floats2half2_rn(p0, p1);
            *(__half2*)(sm + bo + sw128((uint32_t)((r0 + 8) * 128 + kc)))
                = __floats2half2_rn(p2, p3);
        }
        __syncwarp();

        uint32_t pf[8][4];
#pragma unroll
        for (int kt = 0; kt < 8; kt++) {
            uint32_t bo = (kt >= 4) ? PS1_OFF : QS_OFF;
            uint32_t a = smb + bo + sw128((uint32_t)(mrow * 128 + (kt & 3) * 32 + fcol));
            LDSM4(pf[kt], a);
        }
#pragma unroll
        for (int dg = 0; dg < 4; dg++) {
#pragma unroll
            for (int kt = 0; kt < 8; kt++) {
                uint32_t bf[4];
                uint32_t a = smb + VT_OFF + (uint32_t)(2 * c + (kt >> 2)) * 8192u
                           + sw128((uint32_t)((dg * 16 + frow) * 128 + (kt & 3) * 32 + fcol));
                LDSM4(bf, a);
                MMA_F16(oacc[2 * dg],     pf[kt][0], pf[kt][2], pf[kt][1], pf[kt][3], bf[0], bf[1]);
                MMA_F16(oacc[2 * dg + 1], pf[kt][0], pf[kt][2], pf[kt][1], pf[kt][3], bf[2], bf[3]);
            }
        }
        __syncwarp();
    }

    rs0 += __shfl_xor_sync(0xFFFFFFFFu, rs0, 1);
    rs0 += __shfl_xor_sync(0xFFFFFFFFu, rs0, 2);
    rs1 += __shfl_xor_sync(0xFFFFFFFFu, rs1, 1);
    rs1 += __shfl_xor_sync(0xFFFFFFFFu, rs1, 2);
    float inv0 = 1.0f / rs0, inv1 = 1.0f / rs1;

    int q0 = qt * 128 + w * 16 + (l >> 2);
    __half* o0 = O + ((size_t)(b * LQ_ + q0)) * D_ + h * HD_;
    __half* o1 = o0 + 8 * D_;
#pragma unroll
    for (int nt = 0; nt < 8; nt++) {
        int dcol = nt * 8 + 2 * (l & 3);
        *(__half2*)(o0 + dcol) = __floats2half2_rn(oacc[nt][0] * inv0, oacc[nt][1] * inv0);
        *(__half2*)(o1 + dcol) = __floats2half2_rn(oacc[nt][2] * inv1, oacc[nt][3] * inv1);
    }
}

// ---------------------------------------------------------------------------
extern "C" void kernel_launch(void* const* d_in, const int* in_sizes, int n_in,
                              void* d_out, int out_size)
{
    const float* patches = (const float*)d_in[0];
    const float* latents = (const float*)d_in[1];
    const float* Wq = (const float*)d_in[2];
    const float* bq = (const float*)d_in[3];
    const float* Wk = (const float*)d_in[4];
    const float* bk = (const float*)d_in[5];
    const float* Wv = (const float*)d_in[6];
    const float* bv = (const float*)d_in[7];
    const float* Wo = (const float*)d_in[8];
    const float* bo = (const float*)d_in[9];
    const int*   nf = (const int*)d_in[10];
    float* out = (float*)d_out;

    __half *Ph, *Lh, *Qd, *KVd, *Ad, *WtQ, *WtKV, *WtO;
    float *bkv;
    cudaGetSymbolAddress((void**)&Ph,   g_Ph);
    cudaGetSymbolAddress((void**)&Lh,   g_Lh);
    cudaGetSymbolAddress((void**)&Qd,   g_Q);
    cudaGetSymbolAddress((void**)&KVd,  g_KV);
    cudaGetSymbolAddress((void**)&Ad,   g_attn);
    cudaGetSymbolAddress((void**)&WtQ,  g_WtQ);
    cudaGetSymbolAddress((void**)&WtKV, g_WtKV);
    cudaGetSymbolAddress((void**)&WtO,  g_WtO);
    cudaGetSymbolAddress((void**)&bkv,  g_bkv);

    cudaFuncSetAttribute(gemm_f16<__half>, cudaFuncAttributeMaxDynamicSharedMemorySize, GEMM_SMEM);
    cudaFuncSetAttribute(gemm_f16<float>,  cudaFuncAttributeMaxDynamicSharedMemorySize, GEMM_SMEM);
    cudaFuncSetAttribute(attn_kernel, cudaFuncAttributeMaxDynamicSharedMemorySize, ATTN_SMEM);

    // 0) prep (3 launches)
    transpose_all_kernel<<<dim3(32, 32, 3), dim3(32, 8)>>>(Wq, Wk, Wv, Wo, WtQ, WtKV, WtO);
    rope_table_kernel<<<(NF_MAX * 32) / 256, 256>>>(nf, bk, bv);
    int np4 = B_ * LQ_ * D_ / 4;
    int nl4 = B_ * LKV_ * D_ / 4;
    cvt_both_kernel<<<(np4 + nl4 + 255) / 256, 256>>>(patches, latents, Ph, Lh, np4, np4 + nl4);

    // 1) Q projection (half out)
    gemm_f16<__half><<<dim3(D_ / 128, (B_ * LQ_) / 128), 256, GEMM_SMEM>>>(
        Ph, WtQ, bq, Qd, B_ * LQ_, D_, D_);

    // 2) fused K|V projection (half out, N=512)
    gemm_f16<__half><<<dim3(512 / 128, (B_ * LKV_) / 128), 256, GEMM_SMEM>>>(
        Lh, WtKV, bkv, KVd, B_ * LKV_, 512, D_);

    // 3) attention (fp16 mma + fused RoPE, 96KB smem -> 2 CTAs/SM)
    dim3 ga(LQ_ / 128, H_, B_);
    attn_kernel<<<ga, 256, ATTN_SMEM>>>(Qd, KVd, Ad, nf);

    // 4) output projection (float out)
    gemm_f16<float><<<dim3(D_ / 128, (B_ * LQ_) / 128), 256, GEMM_SMEM>>>(
        Ad, WtO, bo, out, B_ * LQ_, D_, D_);
}

// round 12
// speedup vs baseline: 1.3581x; 1.1775x over previous
#include <cuda_runtime.h>
#include <cuda_fp16.h>
#include <math.h>
#include <stdint.h>

#define B_    4
#define LQ_   4096
#define LKV_  256
#define D_    1024
#define H_    16
#define KVH_  4
#define HD_   64
#define NF_MAX 4096

// ---------------- scratch (device globals; no allocation allowed) ----------
__device__ __half g_Ph[(size_t)B_ * LQ_ * D_];          // fp16 patches
__device__ __half g_Lh[(size_t)B_ * LKV_ * D_];         // fp16 latents
__device__ __half g_Q[(size_t)B_ * LQ_ * D_];           // fp16 Q
__device__ __half g_KV[(size_t)B_ * LKV_ * 512];        // fused K|V
__device__ __half g_Kr[(size_t)B_ * KVH_ * 16384];      // rope'd K, pre-swizzled blobs
__device__ __half g_Vt[(size_t)B_ * KVH_ * 16384];      // V^T, pre-swizzled blobs
__device__ __half g_attn[(size_t)B_ * LQ_ * D_];        // fp16 attn out
__device__ __half g_WtQ[(size_t)D_ * D_];               // W^T [N][K] fp16
__device__ __half g_WtKV[(size_t)512 * D_];             // [Wk^T ; Wv^T]
__device__ __half g_WtO[(size_t)D_ * D_];
__device__ float  g_bkv[512];                            // bk | bv
__device__ float  g_rope[2 * NF_MAX * 32];              // cos | sin

// ---------------- helpers ---------------------------------------------------
__device__ __forceinline__ uint32_t smem_u32(const void* p) {
    uint32_t a;
    asm("{ .reg .u64 t; cvta.to.shared.u64 t, %1; cvt.u32.u64 %0, t; }"
        : "=r"(a) : "l"(p));
    return a;
}
__device__ __forceinline__ uint32_t sw128(uint32_t off) {
    return off ^ ((off >> 3) & 0x70);
}

#define CP_A16(d, s) \
    asm volatile("cp.async.cg.shared.global [%0], [%1], 16;" :: "r"(d), "l"(s) : "memory")
#define CP_COMMIT() asm volatile("cp.async.commit_group;" ::: "memory")
#define CP_WAIT1()  asm volatile("cp.async.wait_group 1;" ::: "memory")
#define CP_WAIT0()  asm volatile("cp.async.wait_group 0;" ::: "memory")
#define LDSM4(r, addr) \
    asm volatile("ldmatrix.sync.aligned.m8n8.x4.shared.b16 {%0,%1,%2,%3}, [%4];" \
        : "=r"((r)[0]), "=r"((r)[1]), "=r"((r)[2]), "=r"((r)[3]) : "r"(addr))
#define MMA_F16(d, a0, a1, a2, a3, b0, b1) \
    asm volatile("mma.sync.aligned.m16n8k16.row.col.f32.f16.f16.f32 " \
        "{%0,%1,%2,%3}, {%4,%5,%6,%7}, {%8,%9}, {%0,%1,%2,%3};" \
        : "+f"((d)[0]), "+f"((d)[1]), "+f"((d)[2]), "+f"((d)[3]) \
        : "r"(a0), "r"(a1), "r"(a2), "r"(a3), "r"(b0), "r"(b1))

__device__ __forceinline__ void store2(float* p, float x, float y) {
    *(float2*)p = make_float2(x, y);
}
__device__ __forceinline__ void store2(__half* p, float x, float y) {
    *(__half2*)p = __floats2half2_rn(x, y);
}

// ---------------------------------------------------------------------------
__global__ void cvt_both_kernel(const float* __restrict__ p, const float* __restrict__ l,
                                __half* __restrict__ ph, __half* __restrict__ lh,
                                int np4, int ntot4)
{
    int i = blockIdx.x * blockDim.x + threadIdx.x;
    if (i >= ntot4) return;
    const float* in;
    __half* out;
    int j;
    if (i < np4) { in = p; out = ph; j = i; }
    else         { in = l; out = lh; j = i - np4; }
    float4 v = reinterpret_cast<const float4*>(in)[j];
    reinterpret_cast<__half2*>(out)[2 * j]     = __floats2half2_rn(v.x, v.y);
    reinterpret_cast<__half2*>(out)[2 * j + 1] = __floats2half2_rn(v.z, v.w);
}

__global__ void transpose_all_kernel(const float* __restrict__ Wq, const float* __restrict__ Wk,
                                     const float* __restrict__ Wv, const float* __restrict__ Wo,
                                     __half* __restrict__ WtQ, __half* __restrict__ WtKV,
                                     __half* __restrict__ WtO)
{
    __shared__ float t[32][33];
    int z = blockIdx.z;
    const float* W;
    __half* Wt;
    int N, nb, rowoff = 0;
    if (z == 0)      { W = Wq; Wt = WtQ; N = D_; nb = blockIdx.x * 32; }
    else if (z == 1) { W = Wo; Wt = WtO; N = D_; nb = blockIdx.x * 32; }
    else {
        if (blockIdx.x >= 16) return;
        if (blockIdx.x < 8) { W = Wk; rowoff = 0;   nb = blockIdx.x * 32; }
        else                { W = Wv; rowoff = 256; nb = (blockIdx.x - 8) * 32; }
        Wt = WtKV; N = KVH_ * HD_;
    }
    int kb = blockIdx.y * 32;
    int x = threadIdx.x, y = threadIdx.y;
#pragma unroll
    for (int i = 0; i < 32; i += 8)
        t[y + i][x] = W[(size_t)(kb + y + i) * N + nb + x];
    __syncthreads();
#pragma unroll
    for (int i = 0; i < 32; i += 8)
        Wt[(size_t)(rowoff + nb + y + i) * D_ + kb + x] = __float2half_rn(t[x][y + i]);
}

__global__ void rope_table_kernel(const int* __restrict__ nf_ptr,
                                  const float* __restrict__ bk, const float* __restrict__ bv)
{
    if (blockIdx.x == 0) g_bkv[threadIdx.x] = bk[threadIdx.x];
    if (blockIdx.x == 1) g_bkv[256 + threadIdx.x] = bv[threadIdx.x];
    int nf = *nf_ptr;
    if (nf <= 1 || nf > NF_MAX) return;
    int idx = blockIdx.x * blockDim.x + threadIdx.x;
    if (idx >= nf * 32) return;
    int j = idx & 31, pos = idx >> 5;
    float inv = powf(10000.0f, -(float)(2 * j) / 64.0f);
    float th = (float)pos * inv;
    g_rope[idx] = cosf(th);
    g_rope[NF_MAX * 32 + idx] = sinf(th);
}

// ---------------------------------------------------------------------------
// kv_prep: per (b,kvh) builds pre-swizzled SMEM-image blobs:
//   g_Kr: rope'd K  [256 rows][64 halves], byte off = sw128(row*128 + col*2)
//   g_Vt: V^T 4 sub-blobs of [64 d][64 kv], byte off = sub*8192 + sw128(d*128 + kv*2)
// Bitwise-identical math to the old in-attention load phase.
// ---------------------------------------------------------------------------
__global__ void kv_prep_kernel(const __half* __restrict__ KV, const int* __restrict__ nf_ptr)
{
    int kvh = blockIdx.x, b = blockIdx.y;
    int tid = threadIdx.x;
    int nf = *nf_ptr;
    bool rope = (nf > 1) && (nf <= NF_MAX);
    int kdiv = rope ? (LKV_ / nf) : 1;
    char* kr = (char*)(g_Kr + ((size_t)(b * KVH_ + kvh)) * 16384);
    char* vt = (char*)(g_Vt + ((size_t)(b * KVH_ + kvh)) * 16384);

    // K rope -> swizzled blob
    for (int u = tid; u < 512; u += 256) {
        int row = u >> 1, part = u & 1;
        const __half* src = KV + (size_t)(b * LKV_ + row) * 512 + kvh * HD_;
        int pos = rope ? (row / kdiv) : 0;
        const float* ct = g_rope + pos * 32;
        const float* st = g_rope + NF_MAX * 32 + pos * 32;
#pragma unroll
        for (int jj = 0; jj < 4; jj++) {
            int j = part * 16 + jj * 4;
            __half2 u0 = *(const __half2*)(src + j);
            __half2 u1 = *(const __half2*)(src + j + 2);
            __half2 v0 = *(const __half2*)(src + j + 32);
            __half2 v1 = *(const __half2*)(src + j + 34);
            float a1[4] = { __low2float(u0), __high2float(u0), __low2float(u1), __high2float(u1) };
            float a2[4] = { __low2float(v0), __high2float(v0), __low2float(v1), __high2float(v1) };
            float y1[4], y2[4];
#pragma unroll
            for (int e = 0; e < 4; e++) {
                float c = 1.f, s = 0.f;
                if (rope) { c = ct[j + e], s = st[j + e]; }
                y1[e] = a1[e] * c - a2[e] * s;
                y2[e] = a2[e] * c + a1[e] * s;
            }
            uint32_t o0 = sw128((uint32_t)(row * 128 + j * 2));
            uint32_t o1 = sw128((uint32_t)(row * 128 + (j + 32) * 2));
            ((__half2*)(kr + o0))[0] = __floats2half2_rn(y1[0], y1[1]);
            ((__half2*)(kr + o0))[1] = __floats2half2_rn(y1[2], y1[3]);
            ((__half2*)(kr + o1))[0] = __floats2half2_rn(y2[0], y2[1]);
            ((__half2*)(kr + o1))[1] = __floats2half2_rn(y2[2], y2[3]);
        }
    }

    // V transpose -> swizzled blob
#pragma unroll
    for (int it = 0; it < 8; it++) {
        int idx = it * 256 + tid;
        int kv = idx >> 3, c8 = idx & 7;
        const __half* src = KV + (size_t)(b * LKV_ + kv) * 512 + 256 + kvh * HD_ + c8 * 8;
        uint4 raw = *(const uint4*)src;
        const __half* hv = (const __half*)&raw;
        char* base = vt + (kv >> 6) * 8192;
        int kcol = (kv & 63) * 2;
#pragma unroll
        for (int e = 0; e < 8; e++) {
            int d = c8 * 8 + e;
            *(__half*)(base + sw128((uint32_t)(d * 128 + kcol))) = hv[e];
        }
    }
}

// ---------------------------------------------------------------------------
// fp16 mma.sync GEMM (EXACT round-9 proven version — FROZEN): C = A@Bt^T + bias
// ---------------------------------------------------------------------------
#define GEMM_SMEM (1024 + 4 * 16384)

__device__ __forceinline__ void load_tile(const __half* Ag, const __half* Bg, int K,
                                          uint32_t aBuf, uint32_t bBuf, int tid)
{
#pragma unroll
    for (int j = 0; j < 4; j++) {
        int idx = j * 256 + tid;
        int row = idx >> 3, k8 = idx & 7;
        uint32_t off = sw128((uint32_t)(row * 128 + k8 * 16));
        CP_A16(aBuf + off, Ag + (size_t)row * K + k8 * 8);
        CP_A16(bBuf + off, Bg + (size_t)row * K + k8 * 8);
    }
}

template <typename OutT>
__global__ __launch_bounds__(256)
void gemm_f16(const __half* __restrict__ A, const __half* __restrict__ Bt,
              const float* __restrict__ bias, OutT* __restrict__ C,
              int M, int N, int K)
{
    extern __shared__ char smraw[];
    uint32_t base = smem_u32(smraw);
    uint32_t data = (base + 1023u) & ~1023u;

    int tid = threadIdx.x, lane = tid & 31, wid = tid >> 5;
    int wm = (wid >> 2) * 64;
    int wn = (wid & 3) * 32;

    const __half* Ag = A  + (size_t)blockIdx.y * 128 * K;
    const __half* Bg = Bt + (size_t)blockIdx.x * 128 * K;

    float acc[4][4][4];
#pragma unroll
    for (int i = 0; i < 4; i++)
#pragma unroll
        for (int j = 0; j < 4; j++)
#pragma unroll
            for (int k = 0; k < 4; k++) acc[i][j][k] = 0.f;

    int T = K >> 6;
    load_tile(Ag, Bg, K, data, data + 16384u, tid);
    CP_COMMIT();

    int lmat = lane >> 3, lrow = lane & 7;
    int frow = ((lmat & 2) ? 8 : 0) + lrow;
    int fcol = (lmat & 1) * 16;

    for (int t = 0; t < T; ++t) {
        int st = t & 1;
        if (t + 1 < T) {
            uint32_t nb = data + (uint32_t)((t + 1) & 1) * 32768u;
            load_tile(Ag + (t + 1) * 64, Bg + (t + 1) * 64, K, nb, nb + 16384u, tid);
            CP_COMMIT();
            CP_WAIT1();
        } else {
            CP_WAIT0();
        }
        __syncthreads();

        uint32_t aB = data + (uint32_t)st * 32768u;
        uint32_t bB = aB + 16384u;
#pragma unroll
        for (int kk = 0; kk < 4; ++kk) {
            uint32_t af[4][4], bf[2][4];
#pragma unroll
            for (int mi = 0; mi < 4; ++mi) {
                uint32_t addr = aB + sw128((uint32_t)((wm + mi * 16 + frow) * 128 + kk * 32 + fcol));
                LDSM4(af[mi], addr);
            }
#pragma unroll
            for (int nj = 0; nj < 2; ++nj) {
                uint32_t addr = bB + sw128((uint32_t)((wn + nj * 16 + frow) * 128 + kk * 32 + fcol));
                LDSM4(bf[nj], addr);
            }
#pragma unroll
            for (int mi = 0; mi < 4; ++mi)
#pragma unroll
                for (int ni = 0; ni < 4; ++ni) {
                    int nj = ni >> 1, lh = (ni & 1) * 2;
                    MMA_F16(acc[mi][ni],
                            af[mi][0], af[mi][2], af[mi][1], af[mi][3],
                            bf[nj][lh], bf[nj][lh + 1]);
                }
        }
        __syncthreads();
    }

    int rbase = blockIdx.y * 128 + wm + (lane >> 2);
    int cbase = blockIdx.x * 128 + wn + (lane & 3) * 2;
#pragma unroll
    for (int mi = 0; mi < 4; ++mi) {
#pragma unroll
        for (int ni = 0; ni < 4; ++ni) {
            int c = cbase + ni * 8;
            float2 bv = *(const float2*)(bias + c);
            int r0 = rbase + mi * 16;
            store2(C + (size_t)r0 * N + c, acc[mi][ni][0] + bv.x, acc[mi][ni][1] + bv.y);
            store2(C + (size_t)(r0 + 8) * N + c, acc[mi][ni][2] + bv.x, acc[mi][ni][3] + bv.y);
        }
    }
}

// ---------------------------------------------------------------------------
// fp16 MMA flash attention. grid (LQ/128, H, B), 256 threads, 96KB smem.
// K/V tiles arrive via identity cp.async from pre-swizzled blobs (g_Kr/g_Vt);
// Q rope overlaps the copies. Layout (unchanged):
//   QS/PS0 0 (16KB, aliased)  KS 16384 (32KB)  VT 49152 (32KB)  PS1 81920 (16KB)
// ---------------------------------------------------------------------------
#define QS_OFF 0u
#define KS_OFF 16384u
#define VT_OFF 49152u
#define PS1_OFF 81920u
#define ATTN_SMEM 98304

__global__ __launch_bounds__(256)
void attn_kernel(const __half* __restrict__ Q, __half* __restrict__ O,
                 const int* __restrict__ nf_ptr)
{
    extern __shared__ char sm[];
    uint32_t smb = smem_u32(sm);

    int tid = threadIdx.x, l = tid & 31, w = tid >> 5;
    int b = blockIdx.z, h = blockIdx.y, qt = blockIdx.x;
    int kvh = h >> 2;
    int nf = *nf_ptr;
    bool rope = (nf > 1) && (nf <= NF_MAX);
    int qdiv = rope ? (LQ_ / nf) : 1;

    // ---- issue K/V identity copies first (hide behind Q rope) -------------
    const char* krb = (const char*)(g_Kr + ((size_t)(b * KVH_ + kvh)) * 16384);
    const char* vtb = (const char*)(g_Vt + ((size_t)(b * KVH_ + kvh)) * 16384);
#pragma unroll
    for (int it = 0; it < 8; it++) {
        uint32_t off = (uint32_t)(it * 256 + tid) * 16u;
        CP_A16(smb + KS_OFF + off, krb + off);
        CP_A16(smb + VT_OFF + off, vtb + off);
    }
    CP_COMMIT();

    // ---- Q tile: rope + scale (scalar; overlaps cp.async) ------------------
    {
        int row = tid >> 1, part = tid & 1;
        int qglob = qt * 128 + row;
        const __half* src = Q + ((size_t)(b * LQ_ + qglob)) * D_ + h * HD_;
        int pos = rope ? (qglob / qdiv) : 0;
        const float* ct = g_rope + pos * 32;
        const float* st = g_rope + NF_MAX * 32 + pos * 32;
#pragma unroll
        for (int jj = 0; jj < 4; jj++) {
            int j = part * 16 + jj * 4;
            __half2 u0 = *(const __half2*)(src + j);
            __half2 u1 = *(const __half2*)(src + j + 2);
            __half2 v0 = *(const __half2*)(src + j + 32);
            __half2 v1 = *(const __half2*)(src + j + 34);
            float a1[4] = { __low2float(u0), __high2float(u0), __low2float(u1), __high2float(u1) };
            float a2[4] = { __low2float(v0), __high2float(v0), __low2float(v1), __high2float(v1) };
            float y1[4], y2[4];
#pragma unroll
            for (int e = 0; e < 4; e++) {
                float c = 1.f, s = 0.f;
                if (rope) { c = ct[j + e], s = st[j + e]; }
                y1[e] = (a1[e] * c - a2[e] * s) * 0.125f;
                y2[e] = (a2[e] * c + a1[e] * s) * 0.125f;
            }
            uint32_t o0 = QS_OFF + sw128((uint32_t)(row * 128 + j * 2));
            uint32_t o1 = QS_OFF + sw128((uint32_t)(row * 128 + (j + 32) * 2));
            ((__half2*)(sm + o0))[0] = __floats2half2_rn(y1[0], y1[1]);
            ((__half2*)(sm + o0))[1] = __floats2half2_rn(y1[2], y1[3]);
            ((__half2*)(sm + o1))[0] = __floats2half2_rn(y2[0], y2[1]);
            ((__half2*)(sm + o1))[1] = __floats2half2_rn(y2[2], y2[3]);
        }
    }
    CP_WAIT0();
    __syncthreads();

    // ---- compute ------------------------------------------------------------
    int lmat = l >> 3, lrow = l & 7;
    int frow = ((lmat & 2) ? 8 : 0) + lrow;
    int fcol = (lmat & 1) * 16;
    int mrow = w * 16 + frow;

    uint32_t qf[4][4];
#pragma unroll
    for (int kk = 0; kk < 4; kk++) {
        uint32_t a = smb + QS_OFF + sw128((uint32_t)(mrow * 128 + kk * 32 + fcol));
        LDSM4(qf[kk], a);
    }
    __syncwarp();   // warp holds qf before QS rows are reused as P

    float oacc[8][4];
#pragma unroll
    for (int i = 0; i < 8; i++)
#pragma unroll
        for (int j = 0; j < 4; j++) oacc[i][j] = 0.f;
    float rs0 = 0.f, rs1 = 0.f;

#pragma unroll
    for (int c = 0; c < 2; c++) {
        float sc[16][4];
#pragma unroll
        for (int i = 0; i < 16; i++)
#pragma unroll
            for (int j = 0; j < 4; j++) sc[i][j] = 0.f;

#pragma unroll
        for (int ng = 0; ng < 8; ng++) {
            int kvrow = c * 128 + ng * 16 + frow;
#pragma unroll
            for (int kk = 0; kk < 4; kk++) {
                uint32_t bf[4];
                uint32_t a = smb + KS_OFF + sw128((uint32_t)(kvrow * 128 + kk * 32 + fcol));
                LDSM4(bf, a);
                MMA_F16(sc[2 * ng],     qf[kk][0], qf[kk][2], qf[kk][1], qf[kk][3], bf[0], bf[1]);
                MMA_F16(sc[2 * ng + 1], qf[kk][0], qf[kk][2], qf[kk][1], qf[kk][3], bf[2], bf[3]);
            }
        }

        int r0 = w * 16 + (l >> 2);
#pragma unroll
        for (int nt = 0; nt < 16; nt++) {
            float p0 = __expf(sc[nt][0]);
            float p1 = __expf(sc[nt][1]);
            float p2 = __expf(sc[nt][2]);
            float p3 = __expf(sc[nt][3]);
            rs0 += p0 + p1;
            rs1 += p2 + p3;
            int kvl = nt * 8 + 2 * (l & 3);
            uint32_t bo = (kvl & 64) ? PS1_OFF : QS_OFF;   // P sub0 aliases QS
            int kc = (kvl & 63) * 2;
            *(__half2*)(sm + bo + sw128((uint32_t)(r0 * 128 + kc)))
                = __floats2half2_rn(p0, p1);
            *(__half2*)(sm + bo + sw128((uint32_t)((r0 + 8) * 128 + kc)))
                = __floats2half2_rn(p2, p3);
        }
        __syncwarp();

        uint32_t pf[8][4];
#pragma unroll
        for (int kt = 0; kt < 8; kt++) {
            uint32_t bo = (kt >= 4) ? PS1_OFF : QS_OFF;
            uint32_t a = smb + bo + sw128((uint32_t)(mrow * 128 + (kt & 3) * 32 + fcol));
            LDSM4(pf[kt], a);
        }
#pragma unroll
        for (int dg = 0; dg < 4; dg++) {
#pragma unroll
            for (int kt = 0; kt < 8; kt++) {
                uint32_t bf[4];
                uint32_t a = smb + VT_OFF + (uint32_t)(2 * c + (kt >> 2)) * 8192u
                           + sw128((uint32_t)((dg * 16 + frow) * 128 + (kt & 3) * 32 + fcol));
                LDSM4(bf, a);
                MMA_F16(oacc[2 * dg],     pf[kt][0], pf[kt][2], pf[kt][1], pf[kt][3], bf[0], bf[1]);
                MMA_F16(oacc[2 * dg + 1], pf[kt][0], pf[kt][2], pf[kt][1], pf[kt][3], bf[2], bf[3]);
            }
        }
        __syncwarp();
    }

    rs0 += __shfl_xor_sync(0xFFFFFFFFu, rs0, 1);
    rs0 += __shfl_xor_sync(0xFFFFFFFFu, rs0, 2);
    rs1 += __shfl_xor_sync(0xFFFFFFFFu, rs1, 1);
    rs1 += __shfl_xor_sync(0xFFFFFFFFu, rs1, 2);
    float inv0 = 1.0f / rs0, inv1 = 1.0f / rs1;

    int q0 = qt * 128 + w * 16 + (l >> 2);
    __half* o0 = O + ((size_t)(b * LQ_ + q0)) * D_ + h * HD_;
    __half* o1 = o0 + 8 * D_;
#pragma unroll
    for (int nt = 0; nt < 8; nt++) {
        int dcol = nt * 8 + 2 * (l & 3);
        *(__half2*)(o0 + dcol) = __floats2half2_rn(oacc[nt][0] * inv0, oacc[nt][1] * inv0);
        *(__half2*)(o1 + dcol) = __floats2half2_rn(oacc[nt][2] * inv1, oacc[nt][3] * inv1);
    }
}

// ---------------------------------------------------------------------------
extern "C" void kernel_launch(void* const* d_in, const int* in_sizes, int n_in,
                              void* d_out, int out_size)
{
    const float* patches = (const float*)d_in[0];
    const float* latents = (const float*)d_in[1];
    const float* Wq = (const float*)d_in[2];
    const float* bq = (const float*)d_in[3];
    const float* Wk = (const float*)d_in[4];
    const float* bk = (const float*)d_in[5];
    const float* Wv = (const float*)d_in[6];
    const float* bv = (const float*)d_in[7];
    const float* Wo = (const float*)d_in[8];
    const float* bo = (const float*)d_in[9];
    const int*   nf = (const int*)d_in[10];
    float* out = (float*)d_out;

    __half *Ph, *Lh, *Qd, *KVd, *Ad, *WtQ, *WtKV, *WtO;
    float *bkv;
    cudaGetSymbolAddress((void**)&Ph,   g_Ph);
    cudaGetSymbolAddress((void**)&Lh,   g_Lh);
    cudaGetSymbolAddress((void**)&Qd,   g_Q);
    cudaGetSymbolAddress((void**)&KVd,  g_KV);
    cudaGetSymbolAddress((void**)&Ad,   g_attn);
    cudaGetSymbolAddress((void**)&WtQ,  g_WtQ);
    cudaGetSymbolAddress((void**)&WtKV, g_WtKV);
    cudaGetSymbolAddress((void**)&WtO,  g_WtO);
    cudaGetSymbolAddress((void**)&bkv,  g_bkv);

    cudaFuncSetAttribute(gemm_f16<__half>, cudaFuncAttributeMaxDynamicSharedMemorySize, GEMM_SMEM);
    cudaFuncSetAttribute(gemm_f16<float>,  cudaFuncAttributeMaxDynamicSharedMemorySize, GEMM_SMEM);
    cudaFuncSetAttribute(attn_kernel, cudaFuncAttributeMaxDynamicSharedMemorySize, ATTN_SMEM);

    // 0) prep (3 launches)
    transpose_all_kernel<<<dim3(32, 32, 3), dim3(32, 8)>>>(Wq, Wk, Wv, Wo, WtQ, WtKV, WtO);
    rope_table_kernel<<<(NF_MAX * 32) / 256, 256>>>(nf, bk, bv);
    int np4 = B_ * LQ_ * D_ / 4;
    int nl4 = B_ * LKV_ * D_ / 4;
    cvt_both_kernel<<<(np4 + nl4 + 255) / 256, 256>>>(patches, latents, Ph, Lh, np4, np4 + nl4);

    // 1) Q projection (half out)
    gemm_f16<__half><<<dim3(D_ / 128, (B_ * LQ_) / 128), 256, GEMM_SMEM>>>(
        Ph, WtQ, bq, Qd, B_ * LQ_, D_, D_);

    // 2) fused K|V projection (half out, N=512)
    gemm_f16<__half><<<dim3(512 / 128, (B_ * LKV_) / 128), 256, GEMM_SMEM>>>(
        Lh, WtKV, bkv, KVd, B_ * LKV_, 512, D_);

    // 2b) kv_prep: rope'd K + V^T pre-swizzled blobs (16 CTAs)
    kv_prep_kernel<<<dim3(KVH_, B_), 256>>>(KVd, nf);

    // 3) attention (fp16 mma; K/V via identity cp.async)
    dim3 ga(LQ_ / 128, H_, B_);
    attn_kernel<<<ga, 256, ATTN_SMEM>>>(Qd, Ad, nf);

    // 4) output projection (float out)
    gemm_f16<float><<<dim3(D_ / 128, (B_ * LQ_) / 128), 256, GEMM_SMEM>>>(
        Ad, WtO, bo, out, B_ * LQ_, D_, D_);
}

// round 13
// speedup vs baseline: 1.4172x; 1.0435x over previous
#include <cuda_runtime.h>
#include <cuda_fp16.h>
#include <math.h>
#include <stdint.h>

#define B_    4
#define LQ_   4096
#define LKV_  256
#define D_    1024
#define H_    16
#define KVH_  4
#define HD_   64
#define NF_MAX 4096

// ---------------- scratch (device globals; no allocation allowed) ----------
__device__ __half g_Ph[(size_t)B_ * LQ_ * D_];          // fp16 patches
__device__ __half g_Lh[(size_t)B_ * LKV_ * D_];         // fp16 latents
__device__ __half g_Q[(size_t)B_ * LQ_ * D_];           // fp16 Q
__device__ __half g_KV[(size_t)B_ * LKV_ * 512];        // fused K|V
__device__ __half g_Kr[(size_t)B_ * KVH_ * 16384];      // rope'd K, pre-swizzled blobs
__device__ __half g_Vt[(size_t)B_ * KVH_ * 16384];      // V^T, pre-swizzled blobs
__device__ __half g_attn[(size_t)B_ * LQ_ * D_];        // fp16 attn out
__device__ __half g_WtQ[(size_t)D_ * D_];               // W^T [N][K] fp16
__device__ __half g_WtKV[(size_t)512 * D_];             // [Wk^T ; Wv^T]
__device__ __half g_WtO[(size_t)D_ * D_];
__device__ float  g_bkv[512];                            // bk | bv
__device__ float  g_rope[2 * NF_MAX * 32];              // cos | sin

// ---------------- helpers ---------------------------------------------------
__device__ __forceinline__ uint32_t smem_u32(const void* p) {
    uint32_t a;
    asm("{ .reg .u64 t; cvta.to.shared.u64 t, %1; cvt.u32.u64 %0, t; }"
        : "=r"(a) : "l"(p));
    return a;
}
__device__ __forceinline__ uint32_t sw128(uint32_t off) {
    return off ^ ((off >> 3) & 0x70);
}

#define CP_A16(d, s) \
    asm volatile("cp.async.cg.shared.global [%0], [%1], 16;" :: "r"(d), "l"(s) : "memory")
#define CP_COMMIT() asm volatile("cp.async.commit_group;" ::: "memory")
#define CP_WAIT1()  asm volatile("cp.async.wait_group 1;" ::: "memory")
#define CP_WAIT0()  asm volatile("cp.async.wait_group 0;" ::: "memory")
#define LDSM4(r, addr) \
    asm volatile("ldmatrix.sync.aligned.m8n8.x4.shared.b16 {%0,%1,%2,%3}, [%4];" \
        : "=r"((r)[0]), "=r"((r)[1]), "=r"((r)[2]), "=r"((r)[3]) : "r"(addr))
#define MMA_F16(d, a0, a1, a2, a3, b0, b1) \
    asm volatile("mma.sync.aligned.m16n8k16.row.col.f32.f16.f16.f32 " \
        "{%0,%1,%2,%3}, {%4,%5,%6,%7}, {%8,%9}, {%0,%1,%2,%3};" \
        : "+f"((d)[0]), "+f"((d)[1]), "+f"((d)[2]), "+f"((d)[3]) \
        : "r"(a0), "r"(a1), "r"(a2), "r"(a3), "r"(b0), "r"(b1))

__device__ __forceinline__ void store2(float* p, float x, float y) {
    *(float2*)p = make_float2(x, y);
}
__device__ __forceinline__ void store2(__half* p, float x, float y) {
    *(__half2*)p = __floats2half2_rn(x, y);
}
__device__ __forceinline__ uint32_t pack_h2(float x, float y) {
    __half2 h = __floats2half2_rn(x, y);
    return *(uint32_t*)&h;
}

// ---------------------------------------------------------------------------
__global__ void cvt_both_kernel(const float* __restrict__ p, const float* __restrict__ l,
                                __half* __restrict__ ph, __half* __restrict__ lh,
                                int np4, int ntot4)
{
    int i = blockIdx.x * blockDim.x + threadIdx.x;
    if (i >= ntot4) return;
    const float* in;
    __half* out;
    int j;
    if (i < np4) { in = p; out = ph; j = i; }
    else         { in = l; out = lh; j = i - np4; }
    float4 v = reinterpret_cast<const float4*>(in)[j];
    reinterpret_cast<__half2*>(out)[2 * j]     = __floats2half2_rn(v.x, v.y);
    reinterpret_cast<__half2*>(out)[2 * j + 1] = __floats2half2_rn(v.z, v.w);
}

__global__ void transpose_all_kernel(const float* __restrict__ Wq, const float* __restrict__ Wk,
                                     const float* __restrict__ Wv, const float* __restrict__ Wo,
                                     __half* __restrict__ WtQ, __half* __restrict__ WtKV,
                                     __half* __restrict__ WtO)
{
    __shared__ float t[32][33];
    int z = blockIdx.z;
    const float* W;
    __half* Wt;
    int N, nb, rowoff = 0;
    if (z == 0)      { W = Wq; Wt = WtQ; N = D_; nb = blockIdx.x * 32; }
    else if (z == 1) { W = Wo; Wt = WtO; N = D_; nb = blockIdx.x * 32; }
    else {
        if (blockIdx.x >= 16) return;
        if (blockIdx.x < 8) { W = Wk; rowoff = 0;   nb = blockIdx.x * 32; }
        else                { W = Wv; rowoff = 256; nb = (blockIdx.x - 8) * 32; }
        Wt = WtKV; N = KVH_ * HD_;
    }
    int kb = blockIdx.y * 32;
    int x = threadIdx.x, y = threadIdx.y;
#pragma unroll
    for (int i = 0; i < 32; i += 8)
        t[y + i][x] = W[(size_t)(kb + y + i) * N + nb + x];
    __syncthreads();
#pragma unroll
    for (int i = 0; i < 32; i += 8)
        Wt[(size_t)(rowoff + nb + y + i) * D_ + kb + x] = __float2half_rn(t[x][y + i]);
}

__global__ void rope_table_kernel(const int* __restrict__ nf_ptr,
                                  const float* __restrict__ bk, const float* __restrict__ bv)
{
    if (blockIdx.x == 0) g_bkv[threadIdx.x] = bk[threadIdx.x];
    if (blockIdx.x == 1) g_bkv[256 + threadIdx.x] = bv[threadIdx.x];
    int nf = *nf_ptr;
    if (nf <= 1 || nf > NF_MAX) return;
    int idx = blockIdx.x * blockDim.x + threadIdx.x;
    if (idx >= nf * 32) return;
    int j = idx & 31, pos = idx >> 5;
    float inv = powf(10000.0f, -(float)(2 * j) / 64.0f);
    float th = (float)pos * inv;
    g_rope[idx] = cosf(th);
    g_rope[NF_MAX * 32 + idx] = sinf(th);
}

// ---------------------------------------------------------------------------
// kv_prep (unchanged from R12): pre-swizzled rope'd K and V^T blobs.
// ---------------------------------------------------------------------------
__global__ void kv_prep_kernel(const __half* __restrict__ KV, const int* __restrict__ nf_ptr)
{
    int kvh = blockIdx.x, b = blockIdx.y;
    int tid = threadIdx.x;
    int nf = *nf_ptr;
    bool rope = (nf > 1) && (nf <= NF_MAX);
    int kdiv = rope ? (LKV_ / nf) : 1;
    char* kr = (char*)(g_Kr + ((size_t)(b * KVH_ + kvh)) * 16384);
    char* vt = (char*)(g_Vt + ((size_t)(b * KVH_ + kvh)) * 16384);

    for (int u = tid; u < 512; u += 256) {
        int row = u >> 1, part = u & 1;
        const __half* src = KV + (size_t)(b * LKV_ + row) * 512 + kvh * HD_;
        int pos = rope ? (row / kdiv) : 0;
        const float* ct = g_rope + pos * 32;
        const float* st = g_rope + NF_MAX * 32 + pos * 32;
#pragma unroll
        for (int jj = 0; jj < 4; jj++) {
            int j = part * 16 + jj * 4;
            __half2 u0 = *(const __half2*)(src + j);
            __half2 u1 = *(const __half2*)(src + j + 2);
            __half2 v0 = *(const __half2*)(src + j + 32);
            __half2 v1 = *(const __half2*)(src + j + 34);
            float a1[4] = { __low2float(u0), __high2float(u0), __low2float(u1), __high2float(u1) };
            float a2[4] = { __low2float(v0), __high2float(v0), __low2float(v1), __high2float(v1) };
            float y1[4], y2[4];
#pragma unroll
            for (int e = 0; e < 4; e++) {
                float c = 1.f, s = 0.f;
                if (rope) { c = ct[j + e], s = st[j + e]; }
                y1[e] = a1[e] * c - a2[e] * s;
                y2[e] = a2[e] * c + a1[e] * s;
            }
            uint32_t o0 = sw128((uint32_t)(row * 128 + j * 2));
            uint32_t o1 = sw128((uint32_t)(row * 128 + (j + 32) * 2));
            ((__half2*)(kr + o0))[0] = __floats2half2_rn(y1[0], y1[1]);
            ((__half2*)(kr + o0))[1] = __floats2half2_rn(y1[2], y1[3]);
            ((__half2*)(kr + o1))[0] = __floats2half2_rn(y2[0], y2[1]);
            ((__half2*)(kr + o1))[1] = __floats2half2_rn(y2[2], y2[3]);
        }
    }

#pragma unroll
    for (int it = 0; it < 8; it++) {
        int idx = it * 256 + tid;
        int kv = idx >> 3, c8 = idx & 7;
        const __half* src = KV + (size_t)(b * LKV_ + kv) * 512 + 256 + kvh * HD_ + c8 * 8;
        uint4 raw = *(const uint4*)src;
        const __half* hv = (const __half*)&raw;
        char* base = vt + (kv >> 6) * 8192;
        int kcol = (kv & 63) * 2;
#pragma unroll
        for (int e = 0; e < 8; e++) {
            int d = c8 * 8 + e;
            *(__half*)(base + sw128((uint32_t)(d * 128 + kcol))) = hv[e];
        }
    }
}

// ---------------------------------------------------------------------------
// fp16 mma.sync GEMM (EXACT round-9 proven version — FROZEN): C = A@Bt^T + bias
// ---------------------------------------------------------------------------
#define GEMM_SMEM (1024 + 4 * 16384)

__device__ __forceinline__ void load_tile(const __half* Ag, const __half* Bg, int K,
                                          uint32_t aBuf, uint32_t bBuf, int tid)
{
#pragma unroll
    for (int j = 0; j < 4; j++) {
        int idx = j * 256 + tid;
        int row = idx >> 3, k8 = idx & 7;
        uint32_t off = sw128((uint32_t)(row * 128 + k8 * 16));
        CP_A16(aBuf + off, Ag + (size_t)row * K + k8 * 8);
        CP_A16(bBuf + off, Bg + (size_t)row * K + k8 * 8);
    }
}

template <typename OutT>
__global__ __launch_bounds__(256)
void gemm_f16(const __half* __restrict__ A, const __half* __restrict__ Bt,
              const float* __restrict__ bias, OutT* __restrict__ C,
              int M, int N, int K)
{
    extern __shared__ char smraw[];
    uint32_t base = smem_u32(smraw);
    uint32_t data = (base + 1023u) & ~1023u;

    int tid = threadIdx.x, lane = tid & 31, wid = tid >> 5;
    int wm = (wid >> 2) * 64;
    int wn = (wid & 3) * 32;

    const __half* Ag = A  + (size_t)blockIdx.y * 128 * K;
    const __half* Bg = Bt + (size_t)blockIdx.x * 128 * K;

    float acc[4][4][4];
#pragma unroll
    for (int i = 0; i < 4; i++)
#pragma unroll
        for (int j = 0; j < 4; j++)
#pragma unroll
            for (int k = 0; k < 4; k++) acc[i][j][k] = 0.f;

    int T = K >> 6;
    load_tile(Ag, Bg, K, data, data + 16384u, tid);
    CP_COMMIT();

    int lmat = lane >> 3, lrow = lane & 7;
    int frow = ((lmat & 2) ? 8 : 0) + lrow;
    int fcol = (lmat & 1) * 16;

    for (int t = 0; t < T; ++t) {
        int st = t & 1;
        if (t + 1 < T) {
            uint32_t nb = data + (uint32_t)((t + 1) & 1) * 32768u;
            load_tile(Ag + (t + 1) * 64, Bg + (t + 1) * 64, K, nb, nb + 16384u, tid);
            CP_COMMIT();
            CP_WAIT1();
        } else {
            CP_WAIT0();
        }
        __syncthreads();

        uint32_t aB = data + (uint32_t)st * 32768u;
        uint32_t bB = aB + 16384u;
#pragma unroll
        for (int kk = 0; kk < 4; ++kk) {
            uint32_t af[4][4], bf[2][4];
#pragma unroll
            for (int mi = 0; mi < 4; ++mi) {
                uint32_t addr = aB + sw128((uint32_t)((wm + mi * 16 + frow) * 128 + kk * 32 + fcol));
                LDSM4(af[mi], addr);
            }
#pragma unroll
            for (int nj = 0; nj < 2; ++nj) {
                uint32_t addr = bB + sw128((uint32_t)((wn + nj * 16 + frow) * 128 + kk * 32 + fcol));
                LDSM4(bf[nj], addr);
            }
#pragma unroll
            for (int mi = 0; mi < 4; ++mi)
#pragma unroll
                for (int ni = 0; ni < 4; ++ni) {
                    int nj = ni >> 1, lh = (ni & 1) * 2;
                    MMA_F16(acc[mi][ni],
                            af[mi][0], af[mi][2], af[mi][1], af[mi][3],
                            bf[nj][lh], bf[nj][lh + 1]);
                }
        }
        __syncthreads();
    }

    int rbase = blockIdx.y * 128 + wm + (lane >> 2);
    int cbase = blockIdx.x * 128 + wn + (lane & 3) * 2;
#pragma unroll
    for (int mi = 0; mi < 4; ++mi) {
#pragma unroll
        for (int ni = 0; ni < 4; ++ni) {
            int c = cbase + ni * 8;
            float2 bv = *(const float2*)(bias + c);
            int r0 = rbase + mi * 16;
            store2(C + (size_t)r0 * N + c, acc[mi][ni][0] + bv.x, acc[mi][ni][1] + bv.y);
            store2(C + (size_t)(r0 + 8) * N + c, acc[mi][ni][2] + bv.x, acc[mi][ni][3] + bv.y);
        }
    }
}

// ---------------------------------------------------------------------------
// fp16 MMA flash attention. grid (LQ/128, H, B), 256 threads, 80KB smem.
// P stays in REGISTERS (S accumulator fragment == PV A-operand fragment).
// Softmax via exp2f with log2(e) folded into the Q scale.
//   QS 0 (16KB)  KS 16384 (32KB)  VT 49152 (32KB)
// ---------------------------------------------------------------------------
#define QS_OFF 0u
#define KS_OFF 16384u
#define VT_OFF 49152u
#define ATTN_SMEM 81920

__global__ __launch_bounds__(256)
void attn_kernel(const __half* __restrict__ Q, __half* __restrict__ O,
                 const int* __restrict__ nf_ptr)
{
    extern __shared__ char sm[];
    uint32_t smb = smem_u32(sm);

    int tid = threadIdx.x, l = tid & 31, w = tid >> 5;
    int b = blockIdx.z, h = blockIdx.y, qt = blockIdx.x;
    int kvh = h >> 2;
    int nf = *nf_ptr;
    bool rope = (nf > 1) && (nf <= NF_MAX);
    int qdiv = rope ? (LQ_ / nf) : 1;

    // ---- issue K/V identity copies first (hidden behind Q rope) ------------
    const char* krb = (const char*)(g_Kr + ((size_t)(b * KVH_ + kvh)) * 16384);
    const char* vtb = (const char*)(g_Vt + ((size_t)(b * KVH_ + kvh)) * 16384);
#pragma unroll
    for (int it = 0; it < 8; it++) {
        uint32_t off = (uint32_t)(it * 256 + tid) * 16u;
        CP_A16(smb + KS_OFF + off, krb + off);
        CP_A16(smb + VT_OFF + off, vtb + off);
    }
    CP_COMMIT();

    // ---- Q tile: rope + scale (scale includes log2(e) for exp2 softmax) ----
    const float QSCALE = 0.125f * 1.4426950408889634f;
    {
        int row = tid >> 1, part = tid & 1;
        int qglob = qt * 128 + row;
        const __half* src = Q + ((size_t)(b * LQ_ + qglob)) * D_ + h * HD_;
        int pos = rope ? (qglob / qdiv) : 0;
        const float* ct = g_rope + pos * 32;
        const float* st = g_rope + NF_MAX * 32 + pos * 32;
#pragma unroll
        for (int jj = 0; jj < 4; jj++) {
            int j = part * 16 + jj * 4;
            __half2 u0 = *(const __half2*)(src + j);
            __half2 u1 = *(const __half2*)(src + j + 2);
            __half2 v0 = *(const __half2*)(src + j + 32);
            __half2 v1 = *(const __half2*)(src + j + 34);
            float a1[4] = { __low2float(u0), __high2float(u0), __low2float(u1), __high2float(u1) };
            float a2[4] = { __low2float(v0), __high2float(v0), __low2float(v1), __high2float(v1) };
            float y1[4], y2[4];
#pragma unroll
            for (int e = 0; e < 4; e++) {
                float c = 1.f, s = 0.f;
                if (rope) { c = ct[j + e], s = st[j + e]; }
                y1[e] = (a1[e] * c - a2[e] * s) * QSCALE;
                y2[e] = (a2[e] * c + a1[e] * s) * QSCALE;
            }
            uint32_t o0 = QS_OFF + sw128((uint32_t)(row * 128 + j * 2));
            uint32_t o1 = QS_OFF + sw128((uint32_t)(row * 128 + (j + 32) * 2));
            ((__half2*)(sm + o0))[0] = __floats2half2_rn(y1[0], y1[1]);
            ((__half2*)(sm + o0))[1] = __floats2half2_rn(y1[2], y1[3]);
            ((__half2*)(sm + o1))[0] = __floats2half2_rn(y2[0], y2[1]);
            ((__half2*)(sm + o1))[1] = __floats2half2_rn(y2[2], y2[3]);
        }
    }
    CP_WAIT0();
    __syncthreads();

    // ---- compute ------------------------------------------------------------
    int lmat = l >> 3, lrow = l & 7;
    int frow = ((lmat & 2) ? 8 : 0) + lrow;
    int fcol = (lmat & 1) * 16;
    int mrow = w * 16 + frow;

    uint32_t qf[4][4];
#pragma unroll
    for (int kk = 0; kk < 4; kk++) {
        uint32_t a = smb + QS_OFF + sw128((uint32_t)(mrow * 128 + kk * 32 + fcol));
        LDSM4(qf[kk], a);
    }

    float oacc[8][4];
#pragma unroll
    for (int i = 0; i < 8; i++)
#pragma unroll
        for (int j = 0; j < 4; j++) oacc[i][j] = 0.f;
    float rs0 = 0.f, rs1 = 0.f;

#pragma unroll
    for (int c = 0; c < 2; c++) {
        float sc[16][4];
#pragma unroll
        for (int i = 0; i < 16; i++)
#pragma unroll
            for (int j = 0; j < 4; j++) sc[i][j] = 0.f;

        // S = Q @ K^T for kv chunk [c*128, +128)
#pragma unroll
        for (int ng = 0; ng < 8; ng++) {
            int kvrow = c * 128 + ng * 16 + frow;
#pragma unroll
            for (int kk = 0; kk < 4; kk++) {
                uint32_t bf[4];
                uint32_t a = smb + KS_OFF + sw128((uint32_t)(kvrow * 128 + kk * 32 + fcol));
                LDSM4(bf, a);
                MMA_F16(sc[2 * ng],     qf[kk][0], qf[kk][2], qf[kk][1], qf[kk][3], bf[0], bf[1]);
                MMA_F16(sc[2 * ng + 1], qf[kk][0], qf[kk][2], qf[kk][1], qf[kk][3], bf[2], bf[3]);
            }
        }

        // softmax in registers: p = exp2(s); pack P directly as PV A-fragments.
        // For kv-group kt: a0 = sc[2kt]{0,1}, a1 = sc[2kt]{2,3},
        //                  a2 = sc[2kt+1]{0,1}, a3 = sc[2kt+1]{2,3}
        uint32_t pk[8][4];
#pragma unroll
        for (int kt = 0; kt < 8; kt++) {
            float p00 = exp2f(sc[2 * kt][0]);
            float p01 = exp2f(sc[2 * kt][1]);
            float p02 = exp2f(sc[2 * kt][2]);
            float p03 = exp2f(sc[2 * kt][3]);
            float p10 = exp2f(sc[2 * kt + 1][0]);
            float p11 = exp2f(sc[2 * kt + 1][1]);
            float p12 = exp2f(sc[2 * kt + 1][2]);
            float p13 = exp2f(sc[2 * kt + 1][3]);
            rs0 += (p00 + p01) + (p10 + p11);
            rs1 += (p02 + p03) + (p12 + p13);
            pk[kt][0] = pack_h2(p00, p01);
            pk[kt][1] = pack_h2(p02, p03);
            pk[kt][2] = pack_h2(p10, p11);
            pk[kt][3] = pack_h2(p12, p13);
        }

        // O += P @ V  (P from registers)
#pragma unroll
        for (int dg = 0; dg < 4; dg++) {
#pragma unroll
            for (int kt = 0; kt < 8; kt++) {
                uint32_t bf[4];
                uint32_t a = smb + VT_OFF + (uint32_t)(2 * c + (kt >> 2)) * 8192u
                           + sw128((uint32_t)((dg * 16 + frow) * 128 + (kt & 3) * 32 + fcol));
                LDSM4(bf, a);
                MMA_F16(oacc[2 * dg],     pk[kt][0], pk[kt][1], pk[kt][2], pk[kt][3], bf[0], bf[1]);
                MMA_F16(oacc[2 * dg + 1], pk[kt][0], pk[kt][1], pk[kt][2], pk[kt][3], bf[2], bf[3]);
            }
        }
    }

    rs0 += __shfl_xor_sync(0xFFFFFFFFu, rs0, 1);
    rs0 += __shfl_xor_sync(0xFFFFFFFFu, rs0, 2);
    rs1 += __shfl_xor_sync(0xFFFFFFFFu, rs1, 1);
    rs1 += __shfl_xor_sync(0xFFFFFFFFu, rs1, 2);
    float inv0 = 1.0f / rs0, inv1 = 1.0f / rs1;

    int q0 = qt * 128 + w * 16 + (l >> 2);
    __half* o0 = O + ((size_t)(b * LQ_ + q0)) * D_ + h * HD_;
    __half* o1 = o0 + 8 * D_;
#pragma unroll
    for (int nt = 0; nt < 8; nt++) {
        int dcol = nt * 8 + 2 * (l & 3);
        *(__half2*)(o0 + dcol) = __floats2half2_rn(oacc[nt][0] * inv0, oacc[nt][1] * inv0);
        *(__half2*)(o1 + dcol) = __floats2half2_rn(oacc[nt][2] * inv1, oacc[nt][3] * inv1);
    }
}

// ---------------------------------------------------------------------------
extern "C" void kernel_launch(void* const* d_in, const int* in_sizes, int n_in,
                              void* d_out, int out_size)
{
    const float* patches = (const float*)d_in[0];
    const float* latents = (const float*)d_in[1];
    const float* Wq = (const float*)d_in[2];
    const float* bq = (const float*)d_in[3];
    const float* Wk = (const float*)d_in[4];
    const float* bk = (const float*)d_in[5];
    const float* Wv = (const float*)d_in[6];
    const float* bv = (const float*)d_in[7];
    const float* Wo = (const float*)d_in[8];
    const float* bo = (const float*)d_in[9];
    const int*   nf = (const int*)d_in[10];
    float* out = (float*)d_out;

    __half *Ph, *Lh, *Qd, *KVd, *Ad, *WtQ, *WtKV, *WtO;
    float *bkv;
    cudaGetSymbolAddress((void**)&Ph,   g_Ph);
    cudaGetSymbolAddress((void**)&Lh,   g_Lh);
    cudaGetSymbolAddress((void**)&Qd,   g_Q);
    cudaGetSymbolAddress((void**)&KVd,  g_KV);
    cudaGetSymbolAddress((void**)&Ad,   g_attn);
    cudaGetSymbolAddress((void**)&WtQ,  g_WtQ);
    cudaGetSymbolAddress((void**)&WtKV, g_WtKV);
    cudaGetSymbolAddress((void**)&WtO,  g_WtO);
    cudaGetSymbolAddress((void**)&bkv,  g_bkv);

    cudaFuncSetAttribute(gemm_f16<__half>, cudaFuncAttributeMaxDynamicSharedMemorySize, GEMM_SMEM);
    cudaFuncSetAttribute(gemm_f16<float>,  cudaFuncAttributeMaxDynamicSharedMemorySize, GEMM_SMEM);
    cudaFuncSetAttribute(attn_kernel, cudaFuncAttributeMaxDynamicSharedMemorySize, ATTN_SMEM);

    // 0) prep (3 launches)
    transpose_all_kernel<<<dim3(32, 32, 3), dim3(32, 8)>>>(Wq, Wk, Wv, Wo, WtQ, WtKV, WtO);
    rope_table_kernel<<<(NF_MAX * 32) / 256, 256>>>(nf, bk, bv);
    int np4 = B_ * LQ_ * D_ / 4;
    int nl4 = B_ * LKV_ * D_ / 4;
    cvt_both_kernel<<<(np4 + nl4 + 255) / 256, 256>>>(patches, latents, Ph, Lh, np4, np4 + nl4);

    // 1) Q projection (half out)
    gemm_f16<__half><<<dim3(D_ / 128, (B_ * LQ_) / 128), 256, GEMM_SMEM>>>(
        Ph, WtQ, bq, Qd, B_ * LQ_, D_, D_);

    // 2) fused K|V projection (half out, N=512)
    gemm_f16<__half><<<dim3(512 / 128, (B_ * LKV_) / 128), 256, GEMM_SMEM>>>(
        Lh, WtKV, bkv, KVd, B_ * LKV_, 512, D_);

    // 2b) kv_prep: rope'd K + V^T pre-swizzled blobs (16 CTAs)
    kv_prep_kernel<<<dim3(KVH_, B_), 256>>>(KVd, nf);

    // 3) attention (fp16 mma; P in registers, exp2 softmax)
    dim3 ga(LQ_ / 128, H_, B_);
    attn_kernel<<<ga, 256, ATTN_SMEM>>>(Qd, Ad, nf);

    // 4) output projection (float out)
    gemm_f16<float><<<dim3(D_ / 128, (B_ * LQ_) / 128), 256, GEMM_SMEM>>>(
        Ad, WtO, bo, out, B_ * LQ_, D_, D_);
}

// round 14
// speedup vs baseline: 1.4711x; 1.0380x over previous
#include <cuda_runtime.h>
#include <cuda_fp16.h>
#include <math.h>
#include <stdint.h>

#define B_    4
#define LQ_   4096
#define LKV_  256
#define D_    1024
#define H_    16
#define KVH_  4
#define HD_   64
#define NF_MAX 4096

// ---------------- scratch (device globals; no allocation allowed) ----------
__device__ __half g_Ph[(size_t)B_ * LQ_ * D_];          // fp16 patches
__device__ __half g_Lh[(size_t)B_ * LKV_ * D_];         // fp16 latents
__device__ __half g_Q[(size_t)B_ * LQ_ * D_];           // fp16 Q
__device__ __half g_KV[(size_t)B_ * LKV_ * 512];        // fused K|V
__device__ __half g_Kr[(size_t)B_ * KVH_ * 16384];      // rope'd K, pre-swizzled blobs
__device__ __half g_Vt[(size_t)B_ * KVH_ * 16384];      // V^T, pre-swizzled blobs
__device__ __half g_attn[(size_t)B_ * LQ_ * D_];        // fp16 attn out
__device__ __half g_WtQ[(size_t)D_ * D_];               // W^T [N][K] fp16
__device__ __half g_WtKV[(size_t)512 * D_];             // [Wk^T ; Wv^T]
__device__ __half g_WtO[(size_t)D_ * D_];
__device__ float  g_bkv[512];                            // bk | bv
__device__ float  g_rope[2 * NF_MAX * 32];              // cos | sin

// ---------------- helpers ---------------------------------------------------
__device__ __forceinline__ uint32_t smem_u32(const void* p) {
    uint32_t a;
    asm("{ .reg .u64 t; cvta.to.shared.u64 t, %1; cvt.u32.u64 %0, t; }"
        : "=r"(a) : "l"(p));
    return a;
}
__device__ __forceinline__ uint32_t sw128(uint32_t off) {
    return off ^ ((off >> 3) & 0x70);
}

#define CP_A16(d, s) \
    asm volatile("cp.async.cg.shared.global [%0], [%1], 16;" :: "r"(d), "l"(s) : "memory")
#define CP_COMMIT() asm volatile("cp.async.commit_group;" ::: "memory")
#define CP_WAIT1()  asm volatile("cp.async.wait_group 1;" ::: "memory")
#define CP_WAIT0()  asm volatile("cp.async.wait_group 0;" ::: "memory")
#define LDSM4(r, addr) \
    asm volatile("ldmatrix.sync.aligned.m8n8.x4.shared.b16 {%0,%1,%2,%3}, [%4];" \
        : "=r"((r)[0]), "=r"((r)[1]), "=r"((r)[2]), "=r"((r)[3]) : "r"(addr))
#define MMA_F16(d, a0, a1, a2, a3, b0, b1) \
    asm volatile("mma.sync.aligned.m16n8k16.row.col.f32.f16.f16.f32 " \
        "{%0,%1,%2,%3}, {%4,%5,%6,%7}, {%8,%9}, {%0,%1,%2,%3};" \
        : "+f"((d)[0]), "+f"((d)[1]), "+f"((d)[2]), "+f"((d)[3]) \
        : "r"(a0), "r"(a1), "r"(a2), "r"(a3), "r"(b0), "r"(b1))

__device__ __forceinline__ void store2(float* p, float x, float y) {
    *(float2*)p = make_float2(x, y);
}
__device__ __forceinline__ void store2(__half* p, float x, float y) {
    *(__half2*)p = __floats2half2_rn(x, y);
}
__device__ __forceinline__ uint32_t pack_h2(float x, float y) {
    __half2 h = __floats2half2_rn(x, y);
    return *(uint32_t*)&h;
}

// ---------------------------------------------------------------------------
__global__ void cvt_both_kernel(const float* __restrict__ p, const float* __restrict__ l,
                                __half* __restrict__ ph, __half* __restrict__ lh,
                                int np4, int ntot4)
{
    int i = blockIdx.x * blockDim.x + threadIdx.x;
    if (i >= ntot4) return;
    const float* in;
    __half* out;
    int j;
    if (i < np4) { in = p; out = ph; j = i; }
    else         { in = l; out = lh; j = i - np4; }
    float4 v = reinterpret_cast<const float4*>(in)[j];
    reinterpret_cast<__half2*>(out)[2 * j]     = __floats2half2_rn(v.x, v.y);
    reinterpret_cast<__half2*>(out)[2 * j + 1] = __floats2half2_rn(v.z, v.w);
}

__global__ void transpose_all_kernel(const float* __restrict__ Wq, const float* __restrict__ Wk,
                                     const float* __restrict__ Wv, const float* __restrict__ Wo,
                                     __half* __restrict__ WtQ, __half* __restrict__ WtKV,
                                     __half* __restrict__ WtO)
{
    __shared__ float t[32][33];
    int z = blockIdx.z;
    const float* W;
    __half* Wt;
    int N, nb, rowoff = 0;
    if (z == 0)      { W = Wq; Wt = WtQ; N = D_; nb = blockIdx.x * 32; }
    else if (z == 1) { W = Wo; Wt = WtO; N = D_; nb = blockIdx.x * 32; }
    else {
        if (blockIdx.x >= 16) return;
        if (blockIdx.x < 8) { W = Wk; rowoff = 0;   nb = blockIdx.x * 32; }
        else                { W = Wv; rowoff = 256; nb = (blockIdx.x - 8) * 32; }
        Wt = WtKV; N = KVH_ * HD_;
    }
    int kb = blockIdx.y * 32;
    int x = threadIdx.x, y = threadIdx.y;
#pragma unroll
    for (int i = 0; i < 32; i += 8)
        t[y + i][x] = W[(size_t)(kb + y + i) * N + nb + x];
    __syncthreads();
#pragma unroll
    for (int i = 0; i < 32; i += 8)
        Wt[(size_t)(rowoff + nb + y + i) * D_ + kb + x] = __float2half_rn(t[x][y + i]);
}

__global__ void rope_table_kernel(const int* __restrict__ nf_ptr,
                                  const float* __restrict__ bk, const float* __restrict__ bv)
{
    if (blockIdx.x == 0) g_bkv[threadIdx.x] = bk[threadIdx.x];
    if (blockIdx.x == 1) g_bkv[256 + threadIdx.x] = bv[threadIdx.x];
    int nf = *nf_ptr;
    if (nf <= 1 || nf > NF_MAX) return;
    int idx = blockIdx.x * blockDim.x + threadIdx.x;
    if (idx >= nf * 32) return;
    int j = idx & 31, pos = idx >> 5;
    float inv = powf(10000.0f, -(float)(2 * j) / 64.0f);
    float th = (float)pos * inv;
    g_rope[idx] = cosf(th);
    g_rope[NF_MAX * 32 + idx] = sinf(th);
}

// ---------------------------------------------------------------------------
// kv_prep (unchanged): pre-swizzled rope'd K and V^T blobs per (b,kvh).
// ---------------------------------------------------------------------------
__global__ void kv_prep_kernel(const __half* __restrict__ KV, const int* __restrict__ nf_ptr)
{
    int kvh = blockIdx.x, b = blockIdx.y;
    int tid = threadIdx.x;
    int nf = *nf_ptr;
    bool rope = (nf > 1) && (nf <= NF_MAX);
    int kdiv = rope ? (LKV_ / nf) : 1;
    char* kr = (char*)(g_Kr + ((size_t)(b * KVH_ + kvh)) * 16384);
    char* vt = (char*)(g_Vt + ((size_t)(b * KVH_ + kvh)) * 16384);

    for (int u = tid; u < 512; u += 256) {
        int row = u >> 1, part = u & 1;
        const __half* src = KV + (size_t)(b * LKV_ + row) * 512 + kvh * HD_;
        int pos = rope ? (row / kdiv) : 0;
        const float* ct = g_rope + pos * 32;
        const float* st = g_rope + NF_MAX * 32 + pos * 32;
#pragma unroll
        for (int jj = 0; jj < 4; jj++) {
            int j = part * 16 + jj * 4;
            __half2 u0 = *(const __half2*)(src + j);
            __half2 u1 = *(const __half2*)(src + j + 2);
            __half2 v0 = *(const __half2*)(src + j + 32);
            __half2 v1 = *(const __half2*)(src + j + 34);
            float a1[4] = { __low2float(u0), __high2float(u0), __low2float(u1), __high2float(u1) };
            float a2[4] = { __low2float(v0), __high2float(v0), __low2float(v1), __high2float(v1) };
            float y1[4], y2[4];
#pragma unroll
            for (int e = 0; e < 4; e++) {
                float c = 1.f, s = 0.f;
                if (rope) { c = ct[j + e], s = st[j + e]; }
                y1[e] = a1[e] * c - a2[e] * s;
                y2[e] = a2[e] * c + a1[e] * s;
            }
            uint32_t o0 = sw128((uint32_t)(row * 128 + j * 2));
            uint32_t o1 = sw128((uint32_t)(row * 128 + (j + 32) * 2));
            ((__half2*)(kr + o0))[0] = __floats2half2_rn(y1[0], y1[1]);
            ((__half2*)(kr + o0))[1] = __floats2half2_rn(y1[2], y1[3]);
            ((__half2*)(kr + o1))[0] = __floats2half2_rn(y2[0], y2[1]);
            ((__half2*)(kr + o1))[1] = __floats2half2_rn(y2[2], y2[3]);
        }
    }

#pragma unroll
    for (int it = 0; it < 8; it++) {
        int idx = it * 256 + tid;
        int kv = idx >> 3, c8 = idx & 7;
        const __half* src = KV + (size_t)(b * LKV_ + kv) * 512 + 256 + kvh * HD_ + c8 * 8;
        uint4 raw = *(const uint4*)src;
        const __half* hv = (const __half*)&raw;
        char* base = vt + (kv >> 6) * 8192;
        int kcol = (kv & 63) * 2;
#pragma unroll
        for (int e = 0; e < 8; e++) {
            int d = c8 * 8 + e;
            *(__half*)(base + sw128((uint32_t)(d * 128 + kcol))) = hv[e];
        }
    }
}

// ---------------------------------------------------------------------------
// fp16 mma.sync GEMM (EXACT round-9 proven version — FROZEN): C = A@Bt^T + bias
// ---------------------------------------------------------------------------
#define GEMM_SMEM (1024 + 4 * 16384)

__device__ __forceinline__ void load_tile(const __half* Ag, const __half* Bg, int K,
                                          uint32_t aBuf, uint32_t bBuf, int tid)
{
#pragma unroll
    for (int j = 0; j < 4; j++) {
        int idx = j * 256 + tid;
        int row = idx >> 3, k8 = idx & 7;
        uint32_t off = sw128((uint32_t)(row * 128 + k8 * 16));
        CP_A16(aBuf + off, Ag + (size_t)row * K + k8 * 8);
        CP_A16(bBuf + off, Bg + (size_t)row * K + k8 * 8);
    }
}

template <typename OutT>
__global__ __launch_bounds__(256)
void gemm_f16(const __half* __restrict__ A, const __half* __restrict__ Bt,
              const float* __restrict__ bias, OutT* __restrict__ C,
              int M, int N, int K)
{
    extern __shared__ char smraw[];
    uint32_t base = smem_u32(smraw);
    uint32_t data = (base + 1023u) & ~1023u;

    int tid = threadIdx.x, lane = tid & 31, wid = tid >> 5;
    int wm = (wid >> 2) * 64;
    int wn = (wid & 3) * 32;

    const __half* Ag = A  + (size_t)blockIdx.y * 128 * K;
    const __half* Bg = Bt + (size_t)blockIdx.x * 128 * K;

    float acc[4][4][4];
#pragma unroll
    for (int i = 0; i < 4; i++)
#pragma unroll
        for (int j = 0; j < 4; j++)
#pragma unroll
            for (int k = 0; k < 4; k++) acc[i][j][k] = 0.f;

    int T = K >> 6;
    load_tile(Ag, Bg, K, data, data + 16384u, tid);
    CP_COMMIT();

    int lmat = lane >> 3, lrow = lane & 7;
    int frow = ((lmat & 2) ? 8 : 0) + lrow;
    int fcol = (lmat & 1) * 16;

    for (int t = 0; t < T; ++t) {
        int st = t & 1;
        if (t + 1 < T) {
            uint32_t nb = data + (uint32_t)((t + 1) & 1) * 32768u;
            load_tile(Ag + (t + 1) * 64, Bg + (t + 1) * 64, K, nb, nb + 16384u, tid);
            CP_COMMIT();
            CP_WAIT1();
        } else {
            CP_WAIT0();
        }
        __syncthreads();

        uint32_t aB = data + (uint32_t)st * 32768u;
        uint32_t bB = aB + 16384u;
#pragma unroll
        for (int kk = 0; kk < 4; ++kk) {
            uint32_t af[4][4], bf[2][4];
#pragma unroll
            for (int mi = 0; mi < 4; ++mi) {
                uint32_t addr = aB + sw128((uint32_t)((wm + mi * 16 + frow) * 128 + kk * 32 + fcol));
                LDSM4(af[mi], addr);
            }
#pragma unroll
            for (int nj = 0; nj < 2; ++nj) {
                uint32_t addr = bB + sw128((uint32_t)((wn + nj * 16 + frow) * 128 + kk * 32 + fcol));
                LDSM4(bf[nj], addr);
            }
#pragma unroll
            for (int mi = 0; mi < 4; ++mi)
#pragma unroll
                for (int ni = 0; ni < 4; ++ni) {
                    int nj = ni >> 1, lh = (ni & 1) * 2;
                    MMA_F16(acc[mi][ni],
                            af[mi][0], af[mi][2], af[mi][1], af[mi][3],
                            bf[nj][lh], bf[nj][lh + 1]);
                }
        }
        __syncthreads();
    }

    int rbase = blockIdx.y * 128 + wm + (lane >> 2);
    int cbase = blockIdx.x * 128 + wn + (lane & 3) * 2;
#pragma unroll
    for (int mi = 0; mi < 4; ++mi) {
#pragma unroll
        for (int ni = 0; ni < 4; ++ni) {
            int c = cbase + ni * 8;
            float2 bv = *(const float2*)(bias + c);
            int r0 = rbase + mi * 16;
            store2(C + (size_t)r0 * N + c, acc[mi][ni][0] + bv.x, acc[mi][ni][1] + bv.y);
            store2(C + (size_t)(r0 + 8) * N + c, acc[mi][ni][2] + bv.x, acc[mi][ni][3] + bv.y);
        }
    }
}

// ---------------------------------------------------------------------------
// fp16 MMA flash attention. grid (LQ/128, H, B), 256 threads, 80KB smem.
// KV processed in FOUR 64-row sub-chunks to cap live registers (<128)
// -> 2 CTAs/SM (pinned with launch_bounds(256,2)). P stays in registers.
//   QS 0 (16KB)  KS 16384 (32KB)  VT 49152 (32KB)
// ---------------------------------------------------------------------------
#define QS_OFF 0u
#define KS_OFF 16384u
#define VT_OFF 49152u
#define ATTN_SMEM 81920

__global__ __launch_bounds__(256, 2)
void attn_kernel(const __half* __restrict__ Q, __half* __restrict__ O,
                 const int* __restrict__ nf_ptr)
{
    extern __shared__ char sm[];
    uint32_t smb = smem_u32(sm);

    int tid = threadIdx.x, l = tid & 31, w = tid >> 5;
    int b = blockIdx.z, h = blockIdx.y, qt = blockIdx.x;
    int kvh = h >> 2;
    int nf = *nf_ptr;
    bool rope = (nf > 1) && (nf <= NF_MAX);
    int qdiv = rope ? (LQ_ / nf) : 1;

    // ---- issue K/V identity copies first (hidden behind Q rope) ------------
    const char* krb = (const char*)(g_Kr + ((size_t)(b * KVH_ + kvh)) * 16384);
    const char* vtb = (const char*)(g_Vt + ((size_t)(b * KVH_ + kvh)) * 16384);
#pragma unroll
    for (int it = 0; it < 8; it++) {
        uint32_t off = (uint32_t)(it * 256 + tid) * 16u;
        CP_A16(smb + KS_OFF + off, krb + off);
        CP_A16(smb + VT_OFF + off, vtb + off);
    }
    CP_COMMIT();

    // ---- Q tile: rope + scale (scale includes log2(e) for exp2 softmax) ----
    const float QSCALE = 0.125f * 1.4426950408889634f;
    {
        int row = tid >> 1, part = tid & 1;
        int qglob = qt * 128 + row;
        const __half* src = Q + ((size_t)(b * LQ_ + qglob)) * D_ + h * HD_;
        int pos = rope ? (qglob / qdiv) : 0;
        const float* ct = g_rope + pos * 32;
        const float* st = g_rope + NF_MAX * 32 + pos * 32;
#pragma unroll
        for (int jj = 0; jj < 4; jj++) {
            int j = part * 16 + jj * 4;
            __half2 u0 = *(const __half2*)(src + j);
            __half2 u1 = *(const __half2*)(src + j + 2);
            __half2 v0 = *(const __half2*)(src + j + 32);
            __half2 v1 = *(const __half2*)(src + j + 34);
            float a1[4] = { __low2float(u0), __high2float(u0), __low2float(u1), __high2float(u1) };
            float a2[4] = { __low2float(v0), __high2float(v0), __low2float(v1), __high2float(v1) };
            float y1[4], y2[4];
#pragma unroll
            for (int e = 0; e < 4; e++) {
                float c = 1.f, s = 0.f;
                if (rope) { c = ct[j + e], s = st[j + e]; }
                y1[e] = (a1[e] * c - a2[e] * s) * QSCALE;
                y2[e] = (a2[e] * c + a1[e] * s) * QSCALE;
            }
            uint32_t o0 = QS_OFF + sw128((uint32_t)(row * 128 + j * 2));
            uint32_t o1 = QS_OFF + sw128((uint32_t)(row * 128 + (j + 32) * 2));
            ((__half2*)(sm + o0))[0] = __floats2half2_rn(y1[0], y1[1]);
            ((__half2*)(sm + o0))[1] = __floats2half2_rn(y1[2], y1[3]);
            ((__half2*)(sm + o1))[0] = __floats2half2_rn(y2[0], y2[1]);
            ((__half2*)(sm + o1))[1] = __floats2half2_rn(y2[2], y2[3]);
        }
    }
    CP_WAIT0();
    __syncthreads();

    // ---- compute ------------------------------------------------------------
    int lmat = l >> 3, lrow = l & 7;
    int frow = ((lmat & 2) ? 8 : 0) + lrow;
    int fcol = (lmat & 1) * 16;
    int mrow = w * 16 + frow;

    uint32_t qf[4][4];
#pragma unroll
    for (int kk = 0; kk < 4; kk++) {
        uint32_t a = smb + QS_OFF + sw128((uint32_t)(mrow * 128 + kk * 32 + fcol));
        LDSM4(qf[kk], a);
    }

    float oacc[8][4];
#pragma unroll
    for (int i = 0; i < 8; i++)
#pragma unroll
        for (int j = 0; j < 4; j++) oacc[i][j] = 0.f;
    float rs0 = 0.f, rs1 = 0.f;

#pragma unroll
    for (int cc = 0; cc < 4; cc++) {       // 64 kv rows per sub-chunk
        float sc[8][4];
#pragma unroll
        for (int i = 0; i < 8; i++)
#pragma unroll
            for (int j = 0; j < 4; j++) sc[i][j] = 0.f;

        // S = Q @ K^T for kv rows [cc*64, cc*64+64)
#pragma unroll
        for (int ng = 0; ng < 4; ng++) {
            int kvrow = cc * 64 + ng * 16 + frow;
#pragma unroll
            for (int kk = 0; kk < 4; kk++) {
                uint32_t bf[4];
                uint32_t a = smb + KS_OFF + sw128((uint32_t)(kvrow * 128 + kk * 32 + fcol));
                LDSM4(bf, a);
                MMA_F16(sc[2 * ng],     qf[kk][0], qf[kk][2], qf[kk][1], qf[kk][3], bf[0], bf[1]);
                MMA_F16(sc[2 * ng + 1], qf[kk][0], qf[kk][2], qf[kk][1], qf[kk][3], bf[2], bf[3]);
            }
        }

        // softmax + pack P as PV A-fragments (registers only)
        uint32_t pk[4][4];
#pragma unroll
        for (int kt = 0; kt < 4; kt++) {
            float p00 = exp2f(sc[2 * kt][0]);
            float p01 = exp2f(sc[2 * kt][1]);
            float p02 = exp2f(sc[2 * kt][2]);
            float p03 = exp2f(sc[2 * kt][3]);
            float p10 = exp2f(sc[2 * kt + 1][0]);
            float p11 = exp2f(sc[2 * kt + 1][1]);
            float p12 = exp2f(sc[2 * kt + 1][2]);
            float p13 = exp2f(sc[2 * kt + 1][3]);
            rs0 += (p00 + p01) + (p10 + p11);
            rs1 += (p02 + p03) + (p12 + p13);
            pk[kt][0] = pack_h2(p00, p01);
            pk[kt][1] = pack_h2(p02, p03);
            pk[kt][2] = pack_h2(p10, p11);
            pk[kt][3] = pack_h2(p12, p13);
        }

        // O += P @ V   (VT sub-blob cc covers kv rows [cc*64, cc*64+64))
#pragma unroll
        for (int dg = 0; dg < 4; dg++) {
#pragma unroll
            for (int kt = 0; kt < 4; kt++) {
                uint32_t bf[4];
                uint32_t a = smb + VT_OFF + (uint32_t)cc * 8192u
                           + sw128((uint32_t)((dg * 16 + frow) * 128 + kt * 32 + fcol));
                LDSM4(bf, a);
                MMA_F16(oacc[2 * dg],     pk[kt][0], pk[kt][1], pk[kt][2], pk[kt][3], bf[0], bf[1]);
                MMA_F16(oacc[2 * dg + 1], pk[kt][0], pk[kt][1], pk[kt][2], pk[kt][3], bf[2], bf[3]);
            }
        }
    }

    rs0 += __shfl_xor_sync(0xFFFFFFFFu, rs0, 1);
    rs0 += __shfl_xor_sync(0xFFFFFFFFu, rs0, 2);
    rs1 += __shfl_xor_sync(0xFFFFFFFFu, rs1, 1);
    rs1 += __shfl_xor_sync(0xFFFFFFFFu, rs1, 2);
    float inv0 = 1.0f / rs0, inv1 = 1.0f / rs1;

    int q0 = qt * 128 + w * 16 + (l >> 2);
    __half* o0 = O + ((size_t)(b * LQ_ + q0)) * D_ + h * HD_;
    __half* o1 = o0 + 8 * D_;
#pragma unroll
    for (int nt = 0; nt < 8; nt++) {
        int dcol = nt * 8 + 2 * (l & 3);
        *(__half2*)(o0 + dcol) = __floats2half2_rn(oacc[nt][0] * inv0, oacc[nt][1] * inv0);
        *(__half2*)(o1 + dcol) = __floats2half2_rn(oacc[nt][2] * inv1, oacc[nt][3] * inv1);
    }
}

// ---------------------------------------------------------------------------
extern "C" void kernel_launch(void* const* d_in, const int* in_sizes, int n_in,
                              void* d_out, int out_size)
{
    const float* patches = (const float*)d_in[0];
    const float* latents = (const float*)d_in[1];
    const float* Wq = (const float*)d_in[2];
    const float* bq = (const float*)d_in[3];
    const float* Wk = (const float*)d_in[4];
    const float* bk = (const float*)d_in[5];
    const float* Wv = (const float*)d_in[6];
    const float* bv = (const float*)d_in[7];
    const float* Wo = (const float*)d_in[8];
    const float* bo = (const float*)d_in[9];
    const int*   nf = (const int*)d_in[10];
    float* out = (float*)d_out;

    __half *Ph, *Lh, *Qd, *KVd, *Ad, *WtQ, *WtKV, *WtO;
    float *bkv;
    cudaGetSymbolAddress((void**)&Ph,   g_Ph);
    cudaGetSymbolAddress((void**)&Lh,   g_Lh);
    cudaGetSymbolAddress((void**)&Qd,   g_Q);
    cudaGetSymbolAddress((void**)&KVd,  g_KV);
    cudaGetSymbolAddress((void**)&Ad,   g_attn);
    cudaGetSymbolAddress((void**)&WtQ,  g_WtQ);
    cudaGetSymbolAddress((void**)&WtKV, g_WtKV);
    cudaGetSymbolAddress((void**)&WtO,  g_WtO);
    cudaGetSymbolAddress((void**)&bkv,  g_bkv);

    cudaFuncSetAttribute(gemm_f16<__half>, cudaFuncAttributeMaxDynamicSharedMemorySize, GEMM_SMEM);
    cudaFuncSetAttribute(gemm_f16<float>,  cudaFuncAttributeMaxDynamicSharedMemorySize, GEMM_SMEM);
    cudaFuncSetAttribute(attn_kernel, cudaFuncAttributeMaxDynamicSharedMemorySize, ATTN_SMEM);

    // 0) prep (3 launches)
    transpose_all_kernel<<<dim3(32, 32, 3), dim3(32, 8)>>>(Wq, Wk, Wv, Wo, WtQ, WtKV, WtO);
    rope_table_kernel<<<(NF_MAX * 32) / 256, 256>>>(nf, bk, bv);
    int np4 = B_ * LQ_ * D_ / 4;
    int nl4 = B_ * LKV_ * D_ / 4;
    cvt_both_kernel<<<(np4 + nl4 + 255) / 256, 256>>>(patches, latents, Ph, Lh, np4, np4 + nl4);

    // 1) Q projection (half out)
    gemm_f16<__half><<<dim3(D_ / 128, (B_ * LQ_) / 128), 256, GEMM_SMEM>>>(
        Ph, WtQ, bq, Qd, B_ * LQ_, D_, D_);

    // 2) fused K|V projection (half out, N=512)
    gemm_f16<__half><<<dim3(512 / 128, (B_ * LKV_) / 128), 256, GEMM_SMEM>>>(
        Lh, WtKV, bkv, KVd, B_ * LKV_, 512, D_);

    // 2b) kv_prep: rope'd K + V^T pre-swizzled blobs (16 CTAs)
    kv_prep_kernel<<<dim3(KVH_, B_), 256>>>(KVd, nf);

    // 3) attention (fp16 mma; P in registers; 2 CTAs/SM)
    dim3 ga(LQ_ / 128, H_, B_);
    attn_kernel<<<ga, 256, ATTN_SMEM>>>(Qd, Ad, nf);

    // 4) output projection (float out)
    gemm_f16<float><<<dim3(D_ / 128, (B_ * LQ_) / 128), 256, GEMM_SMEM>>>(
        Ad, WtO, bo, out, B_ * LQ_, D_, D_);
}

// round 15
// speedup vs baseline: 1.4855x; 1.0098x over previous
#include <cuda_runtime.h>
#include <cuda_fp16.h>
#include <math.h>
#include <stdint.h>

#define B_    4
#define LQ_   4096
#define LKV_  256
#define D_    1024
#define H_    16
#define KVH_  4
#define HD_   64
#define NF_MAX 4096

// ---------------- scratch (device globals; no allocation allowed) ----------
__device__ __half g_Ph[(size_t)B_ * LQ_ * D_];          // fp16 patches
__device__ __half g_Lh[(size_t)B_ * LKV_ * D_];         // fp16 latents
__device__ __half g_Q[(size_t)B_ * LQ_ * D_];           // fp16 Q
__device__ __half g_KV[(size_t)B_ * LKV_ * 512];        // fused K|V
__device__ __half g_Kr[(size_t)B_ * KVH_ * 16384];      // rope'd K, pre-swizzled blobs
__device__ __half g_Vt[(size_t)B_ * KVH_ * 16384];      // V^T, pre-swizzled blobs
__device__ __half g_attn[(size_t)B_ * LQ_ * D_];        // fp16 attn out
__device__ __half g_WtQ[(size_t)D_ * D_];               // W^T [N][K] fp16
__device__ __half g_WtKV[(size_t)512 * D_];             // [Wk^T ; Wv^T]
__device__ __half g_WtO[(size_t)D_ * D_];
__device__ float  g_bkv[512];                            // bk | bv
__device__ float  g_rope[2 * NF_MAX * 32];              // cos | sin

// ---------------- helpers ---------------------------------------------------
__device__ __forceinline__ uint32_t smem_u32(const void* p) {
    uint32_t a;
    asm("{ .reg .u64 t; cvta.to.shared.u64 t, %1; cvt.u32.u64 %0, t; }"
        : "=r"(a) : "l"(p));
    return a;
}
__device__ __forceinline__ uint32_t sw128(uint32_t off) {
    return off ^ ((off >> 3) & 0x70);
}

#define CP_A16(d, s) \
    asm volatile("cp.async.cg.shared.global [%0], [%1], 16;" :: "r"(d), "l"(s) : "memory")
#define CP_COMMIT() asm volatile("cp.async.commit_group;" ::: "memory")
#define CP_WAIT0()  asm volatile("cp.async.wait_group 0;" ::: "memory")
#define LDSM4(r, addr) \
    asm volatile("ldmatrix.sync.aligned.m8n8.x4.shared.b16 {%0,%1,%2,%3}, [%4];" \
        : "=r"((r)[0]), "=r"((r)[1]), "=r"((r)[2]), "=r"((r)[3]) : "r"(addr))
#define MMA_F16(d, a0, a1, a2, a3, b0, b1) \
    asm volatile("mma.sync.aligned.m16n8k16.row.col.f32.f16.f16.f32 " \
        "{%0,%1,%2,%3}, {%4,%5,%6,%7}, {%8,%9}, {%0,%1,%2,%3};" \
        : "+f"((d)[0]), "+f"((d)[1]), "+f"((d)[2]), "+f"((d)[3]) \
        : "r"(a0), "r"(a1), "r"(a2), "r"(a3), "r"(b0), "r"(b1))

__device__ __forceinline__ void store2(float* p, float x, float y) {
    *(float2*)p = make_float2(x, y);
}
__device__ __forceinline__ void store2(__half* p, float x, float y) {
    *(__half2*)p = __floats2half2_rn(x, y);
}
__device__ __forceinline__ uint32_t pack_h2(float x, float y) {
    __half2 h = __floats2half2_rn(x, y);
    return *(uint32_t*)&h;
}

// ---------------------------------------------------------------------------
__global__ void cvt_both_kernel(const float* __restrict__ p, const float* __restrict__ l,
                                __half* __restrict__ ph, __half* __restrict__ lh,
                                int np4, int ntot4)
{
    int i = blockIdx.x * blockDim.x + threadIdx.x;
    if (i >= ntot4) return;
    const float* in;
    __half* out;
    int j;
    if (i < np4) { in = p; out = ph; j = i; }
    else         { in = l; out = lh; j = i - np4; }
    float4 v = reinterpret_cast<const float4*>(in)[j];
    reinterpret_cast<__half2*>(out)[2 * j]     = __floats2half2_rn(v.x, v.y);
    reinterpret_cast<__half2*>(out)[2 * j + 1] = __floats2half2_rn(v.z, v.w);
}

__global__ void transpose_all_kernel(const float* __restrict__ Wq, const float* __restrict__ Wk,
                                     const float* __restrict__ Wv, const float* __restrict__ Wo,
                                     __half* __restrict__ WtQ, __half* __restrict__ WtKV,
                                     __half* __restrict__ WtO)
{
    __shared__ float t[32][33];
    int z = blockIdx.z;
    const float* W;
    __half* Wt;
    int N, nb, rowoff = 0;
    if (z == 0)      { W = Wq; Wt = WtQ; N = D_; nb = blockIdx.x * 32; }
    else if (z == 1) { W = Wo; Wt = WtO; N = D_; nb = blockIdx.x * 32; }
    else {
        if (blockIdx.x >= 16) return;
        if (blockIdx.x < 8) { W = Wk; rowoff = 0;   nb = blockIdx.x * 32; }
        else                { W = Wv; rowoff = 256; nb = (blockIdx.x - 8) * 32; }
        Wt = WtKV; N = KVH_ * HD_;
    }
    int kb = blockIdx.y * 32;
    int x = threadIdx.x, y = threadIdx.y;
#pragma unroll
    for (int i = 0; i < 32; i += 8)
        t[y + i][x] = W[(size_t)(kb + y + i) * N + nb + x];
    __syncthreads();
#pragma unroll
    for (int i = 0; i < 32; i += 8)
        Wt[(size_t)(rowoff + nb + y + i) * D_ + kb + x] = __float2half_rn(t[x][y + i]);
}

__global__ void rope_table_kernel(const int* __restrict__ nf_ptr,
                                  const float* __restrict__ bk, const float* __restrict__ bv)
{
    if (blockIdx.x == 0) g_bkv[threadIdx.x] = bk[threadIdx.x];
    if (blockIdx.x == 1) g_bkv[256 + threadIdx.x] = bv[threadIdx.x];
    int nf = *nf_ptr;
    if (nf <= 1 || nf > NF_MAX) return;
    int idx = blockIdx.x * blockDim.x + threadIdx.x;
    if (idx >= nf * 32) return;
    int j = idx & 31, pos = idx >> 5;
    float inv = powf(10000.0f, -(float)(2 * j) / 64.0f);
    float th = (float)pos * inv;
    g_rope[idx] = cosf(th);
    g_rope[NF_MAX * 32 + idx] = sinf(th);
}

// ---------------------------------------------------------------------------
// kv_prep (unchanged): pre-swizzled rope'd K and V^T blobs per (b,kvh).
// ---------------------------------------------------------------------------
__global__ void kv_prep_kernel(const __half* __restrict__ KV, const int* __restrict__ nf_ptr)
{
    int kvh = blockIdx.x, b = blockIdx.y;
    int tid = threadIdx.x;
    int nf = *nf_ptr;
    bool rope = (nf > 1) && (nf <= NF_MAX);
    int kdiv = rope ? (LKV_ / nf) : 1;
    char* kr = (char*)(g_Kr + ((size_t)(b * KVH_ + kvh)) * 16384);
    char* vt = (char*)(g_Vt + ((size_t)(b * KVH_ + kvh)) * 16384);

    for (int u = tid; u < 512; u += 256) {
        int row = u >> 1, part = u & 1;
        const __half* src = KV + (size_t)(b * LKV_ + row) * 512 + kvh * HD_;
        int pos = rope ? (row / kdiv) : 0;
        const float* ct = g_rope + pos * 32;
        const float* st = g_rope + NF_MAX * 32 + pos * 32;
#pragma unroll
        for (int jj = 0; jj < 4; jj++) {
            int j = part * 16 + jj * 4;
            __half2 u0 = *(const __half2*)(src + j);
            __half2 u1 = *(const __half2*)(src + j + 2);
            __half2 v0 = *(const __half2*)(src + j + 32);
            __half2 v1 = *(const __half2*)(src + j + 34);
            float a1[4] = { __low2float(u0), __high2float(u0), __low2float(u1), __high2float(u1) };
            float a2[4] = { __low2float(v0), __high2float(v0), __low2float(v1), __high2float(v1) };
            float y1[4], y2[4];
#pragma unroll
            for (int e = 0; e < 4; e++) {
                float c = 1.f, s = 0.f;
                if (rope) { c = ct[j + e], s = st[j + e]; }
                y1[e] = a1[e] * c - a2[e] * s;
                y2[e] = a2[e] * c + a1[e] * s;
            }
            uint32_t o0 = sw128((uint32_t)(row * 128 + j * 2));
            uint32_t o1 = sw128((uint32_t)(row * 128 + (j + 32) * 2));
            ((__half2*)(kr + o0))[0] = __floats2half2_rn(y1[0], y1[1]);
            ((__half2*)(kr + o0))[1] = __floats2half2_rn(y1[2], y1[3]);
            ((__half2*)(kr + o1))[0] = __floats2half2_rn(y2[0], y2[1]);
            ((__half2*)(kr + o1))[1] = __floats2half2_rn(y2[2], y2[3]);
        }
    }

#pragma unroll
    for (int it = 0; it < 8; it++) {
        int idx = it * 256 + tid;
        int kv = idx >> 3, c8 = idx & 7;
        const __half* src = KV + (size_t)(b * LKV_ + kv) * 512 + 256 + kvh * HD_ + c8 * 8;
        uint4 raw = *(const uint4*)src;
        const __half* hv = (const __half*)&raw;
        char* base = vt + (kv >> 6) * 8192;
        int kcol = (kv & 63) * 2;
#pragma unroll
        for (int e = 0; e < 8; e++) {
            int d = c8 * 8 + e;
            *(__half*)(base + sw128((uint32_t)(d * 128 + kcol))) = hv[e];
        }
    }
}

// ---------------------------------------------------------------------------
// fp16 mma.sync GEMM: C = A @ Bt^T + bias. CTA 128x128, 8 warps (64x32),
// BK=64 halves, 2-buffer cp.async, SINGLE __syncthreads per iteration
// (wait-all -> barrier -> issue next loads -> compute). Pinned 2 CTAs/SM.
// ---------------------------------------------------------------------------
#define GEMM_SMEM (1024 + 4 * 16384)

__device__ __forceinline__ void load_tile(const __half* Ag, const __half* Bg, int K,
                                          uint32_t aBuf, uint32_t bBuf, int tid)
{
#pragma unroll
    for (int j = 0; j < 4; j++) {
        int idx = j * 256 + tid;
        int row = idx >> 3, k8 = idx & 7;
        uint32_t off = sw128((uint32_t)(row * 128 + k8 * 16));
        CP_A16(aBuf + off, Ag + (size_t)row * K + k8 * 8);
        CP_A16(bBuf + off, Bg + (size_t)row * K + k8 * 8);
    }
}

template <typename OutT>
__global__ __launch_bounds__(256, 2)
void gemm_f16(const __half* __restrict__ A, const __half* __restrict__ Bt,
              const float* __restrict__ bias, OutT* __restrict__ C,
              int M, int N, int K)
{
    extern __shared__ char smraw[];
    uint32_t base = smem_u32(smraw);
    uint32_t data = (base + 1023u) & ~1023u;

    int tid = threadIdx.x, lane = tid & 31, wid = tid >> 5;
    int wm = (wid >> 2) * 64;
    int wn = (wid & 3) * 32;

    const __half* Ag = A  + (size_t)blockIdx.y * 128 * K;
    const __half* Bg = Bt + (size_t)blockIdx.x * 128 * K;

    float acc[4][4][4];
#pragma unroll
    for (int i = 0; i < 4; i++)
#pragma unroll
        for (int j = 0; j < 4; j++)
#pragma unroll
            for (int k = 0; k < 4; k++) acc[i][j][k] = 0.f;

    int T = K >> 6;
    load_tile(Ag, Bg, K, data, data + 16384u, tid);
    CP_COMMIT();

    int lmat = lane >> 3, lrow = lane & 7;
    int frow = ((lmat & 2) ? 8 : 0) + lrow;
    int fcol = (lmat & 1) * 16;

    for (int t = 0; t < T; ++t) {
        CP_WAIT0();          // stage t resident (all committed loads done)
        __syncthreads();     // visible to all; all warps done reading buf (t+1)&1

        if (t + 1 < T) {     // issue loads for t+1 BEFORE compute (overlaps MMA)
            uint32_t nb = data + (uint32_t)((t + 1) & 1) * 32768u;
            load_tile(Ag + (t + 1) * 64, Bg + (t + 1) * 64, K, nb, nb + 16384u, tid);
            CP_COMMIT();
        }

        uint32_t aB = data + (uint32_t)(t & 1) * 32768u;
        uint32_t bB = aB + 16384u;
#pragma unroll
        for (int kk = 0; kk < 4; ++kk) {
            uint32_t af[4][4], bf[2][4];
#pragma unroll
            for (int mi = 0; mi < 4; ++mi) {
                uint32_t addr = aB + sw128((uint32_t)((wm + mi * 16 + frow) * 128 + kk * 32 + fcol));
                LDSM4(af[mi], addr);
            }
#pragma unroll
            for (int nj = 0; nj < 2; ++nj) {
                uint32_t addr = bB + sw128((uint32_t)((wn + nj * 16 + frow) * 128 + kk * 32 + fcol));
                LDSM4(bf[nj], addr);
            }
#pragma unroll
            for (int mi = 0; mi < 4; ++mi)
#pragma unroll
                for (int ni = 0; ni < 4; ++ni) {
                    int nj = ni >> 1, lh = (ni & 1) * 2;
                    MMA_F16(acc[mi][ni],
                            af[mi][0], af[mi][2], af[mi][1], af[mi][3],
                            bf[nj][lh], bf[nj][lh + 1]);
                }
        }
    }

    int rbase = blockIdx.y * 128 + wm + (lane >> 2);
    int cbase = blockIdx.x * 128 + wn + (lane & 3) * 2;
#pragma unroll
    for (int mi = 0; mi < 4; ++mi) {
#pragma unroll
        for (int ni = 0; ni < 4; ++ni) {
            int c = cbase + ni * 8;
            float2 bv = *(const float2*)(bias + c);
            int r0 = rbase + mi * 16;
            store2(C + (size_t)r0 * N + c, acc[mi][ni][0] + bv.x, acc[mi][ni][1] + bv.y);
            store2(C + (size_t)(r0 + 8) * N + c, acc[mi][ni][2] + bv.x, acc[mi][ni][3] + bv.y);
        }
    }
}

// ---------------------------------------------------------------------------
// fp16 MMA flash attention (EXACT round-14 version — FROZEN).
// grid (LQ/128, H, B), 256 threads, 80KB smem, 2 CTAs/SM, P in registers.
//   QS 0 (16KB)  KS 16384 (32KB)  VT 49152 (32KB)
// ---------------------------------------------------------------------------
#define QS_OFF 0u
#define KS_OFF 16384u
#define VT_OFF 49152u
#define ATTN_SMEM 81920

__global__ __launch_bounds__(256, 2)
void attn_kernel(const __half* __restrict__ Q, __half* __restrict__ O,
                 const int* __restrict__ nf_ptr)
{
    extern __shared__ char sm[];
    uint32_t smb = smem_u32(sm);

    int tid = threadIdx.x, l = tid & 31, w = tid >> 5;
    int b = blockIdx.z, h = blockIdx.y, qt = blockIdx.x;
    int kvh = h >> 2;
    int nf = *nf_ptr;
    bool rope = (nf > 1) && (nf <= NF_MAX);
    int qdiv = rope ? (LQ_ / nf) : 1;

    // ---- issue K/V identity copies first (hidden behind Q rope) ------------
    const char* krb = (const char*)(g_Kr + ((size_t)(b * KVH_ + kvh)) * 16384);
    const char* vtb = (const char*)(g_Vt + ((size_t)(b * KVH_ + kvh)) * 16384);
#pragma unroll
    for (int it = 0; it < 8; it++) {
        uint32_t off = (uint32_t)(it * 256 + tid) * 16u;
        CP_A16(smb + KS_OFF + off, krb + off);
        CP_A16(smb + VT_OFF + off, vtb + off);
    }
    CP_COMMIT();

    // ---- Q tile: rope + scale (scale includes log2(e) for exp2 softmax) ----
    const float QSCALE = 0.125f * 1.4426950408889634f;
    {
        int row = tid >> 1, part = tid & 1;
        int qglob = qt * 128 + row;
        const __half* src = Q + ((size_t)(b * LQ_ + qglob)) * D_ + h * HD_;
        int pos = rope ? (qglob / qdiv) : 0;
        const float* ct = g_rope + pos * 32;
        const float* st = g_rope + NF_MAX * 32 + pos * 32;
#pragma unroll
        for (int jj = 0; jj < 4; jj++) {
            int j = part * 16 + jj * 4;
            __half2 u0 = *(const __half2*)(src + j);
            __half2 u1 = *(const __half2*)(src + j + 2);
            __half2 v0 = *(const __half2*)(src + j + 32);
            __half2 v1 = *(const __half2*)(src + j + 34);
            float a1[4] = { __low2float(u0), __high2float(u0), __low2float(u1), __high2float(u1) };
            float a2[4] = { __low2float(v0), __high2float(v0), __low2float(v1), __high2float(v1) };
            float y1[4], y2[4];
#pragma unroll
            for (int e = 0; e < 4; e++) {
                float c = 1.f, s = 0.f;
                if (rope) { c = ct[j + e], s = st[j + e]; }
                y1[e] = (a1[e] * c - a2[e] * s) * QSCALE;
                y2[e] = (a2[e] * c + a1[e] * s) * QSCALE;
            }
            uint32_t o0 = QS_OFF + sw128((uint32_t)(row * 128 + j * 2));
            uint32_t o1 = QS_OFF + sw128((uint32_t)(row * 128 + (j + 32) * 2));
            ((__half2*)(sm + o0))[0] = __floats2half2_rn(y1[0], y1[1]);
            ((__half2*)(sm + o0))[1] = __floats2half2_rn(y1[2], y1[3]);
            ((__half2*)(sm + o1))[0] = __floats2half2_rn(y2[0], y2[1]);
            ((__half2*)(sm + o1))[1] = __floats2half2_rn(y2[2], y2[3]);
        }
    }
    CP_WAIT0();
    __syncthreads();

    // ---- compute ------------------------------------------------------------
    int lmat = l >> 3, lrow = l & 7;
    int frow = ((lmat & 2) ? 8 : 0) + lrow;
    int fcol = (lmat & 1) * 16;
    int mrow = w * 16 + frow;

    uint32_t qf[4][4];
#pragma unroll
    for (int kk = 0; kk < 4; kk++) {
        uint32_t a = smb + QS_OFF + sw128((uint32_t)(mrow * 128 + kk * 32 + fcol));
        LDSM4(qf[kk], a);
    }

    float oacc[8][4];
#pragma unroll
    for (int i = 0; i < 8; i++)
#pragma unroll
        for (int j = 0; j < 4; j++) oacc[i][j] = 0.f;
    float rs0 = 0.f, rs1 = 0.f;

#pragma unroll
    for (int cc = 0; cc < 4; cc++) {       // 64 kv rows per sub-chunk
        float sc[8][4];
#pragma unroll
        for (int i = 0; i < 8; i++)
#pragma unroll
            for (int j = 0; j < 4; j++) sc[i][j] = 0.f;

#pragma unroll
        for (int ng = 0; ng < 4; ng++) {
            int kvrow = cc * 64 + ng * 16 + frow;
#pragma unroll
            for (int kk = 0; kk < 4; kk++) {
                uint32_t bf[4];
                uint32_t a = smb + KS_OFF + sw128((uint32_t)(kvrow * 128 + kk * 32 + fcol));
                LDSM4(bf, a);
                MMA_F16(sc[2 * ng],     qf[kk][0], qf[kk][2], qf[kk][1], qf[kk][3], bf[0], bf[1]);
                MMA_F16(sc[2 * ng + 1], qf[kk][0], qf[kk][2], qf[kk][1], qf[kk][3], bf[2], bf[3]);
            }
        }

        uint32_t pk[4][4];
#pragma unroll
        for (int kt = 0; kt < 4; kt++) {
            float p00 = exp2f(sc[2 * kt][0]);
            float p01 = exp2f(sc[2 * kt][1]);
            float p02 = exp2f(sc[2 * kt][2]);
            float p03 = exp2f(sc[2 * kt][3]);
            float p10 = exp2f(sc[2 * kt + 1][0]);
            float p11 = exp2f(sc[2 * kt + 1][1]);
            float p12 = exp2f(sc[2 * kt + 1][2]);
            float p13 = exp2f(sc[2 * kt + 1][3]);
            rs0 += (p00 + p01) + (p10 + p11);
            rs1 += (p02 + p03) + (p12 + p13);
            pk[kt][0] = pack_h2(p00, p01);
            pk[kt][1] = pack_h2(p02, p03);
            pk[kt][2] = pack_h2(p10, p11);
            pk[kt][3] = pack_h2(p12, p13);
        }

#pragma unroll
        for (int dg = 0; dg < 4; dg++) {
#pragma unroll
            for (int kt = 0; kt < 4; kt++) {
                uint32_t bf[4];
                uint32_t a = smb + VT_OFF + (uint32_t)cc * 8192u
                           + sw128((uint32_t)((dg * 16 + frow) * 128 + kt * 32 + fcol));
                LDSM4(bf, a);
                MMA_F16(oacc[2 * dg],     pk[kt][0], pk[kt][1], pk[kt][2], pk[kt][3], bf[0], bf[1]);
                MMA_F16(oacc[2 * dg + 1], pk[kt][0], pk[kt][1], pk[kt][2], pk[kt][3], bf[2], bf[3]);
            }
        }
    }

    rs0 += __shfl_xor_sync(0xFFFFFFFFu, rs0, 1);
    rs0 += __shfl_xor_sync(0xFFFFFFFFu, rs0, 2);
    rs1 += __shfl_xor_sync(0xFFFFFFFFu, rs1, 1);
    rs1 += __shfl_xor_sync(0xFFFFFFFFu, rs1, 2);
    float inv0 = 1.0f / rs0, inv1 = 1.0f / rs1;

    int q0 = qt * 128 + w * 16 + (l >> 2);
    __half* o0 = O + ((size_t)(b * LQ_ + q0)) * D_ + h * HD_;
    __half* o1 = o0 + 8 * D_;
#pragma unroll
    for (int nt = 0; nt < 8; nt++) {
        int dcol = nt * 8 + 2 * (l & 3);
        *(__half2*)(o0 + dcol) = __floats2half2_rn(oacc[nt][0] * inv0, oacc[nt][1] * inv0);
        *(__half2*)(o1 + dcol) = __floats2half2_rn(oacc[nt][2] * inv1, oacc[nt][3] * inv1);
    }
}

// ---------------------------------------------------------------------------
extern "C" void kernel_launch(void* const* d_in, const int* in_sizes, int n_in,
                              void* d_out, int out_size)
{
    const float* patches = (const float*)d_in[0];
    const float* latents = (const float*)d_in[1];
    const float* Wq = (const float*)d_in[2];
    const float* bq = (const float*)d_in[3];
    const float* Wk = (const float*)d_in[4];
    const float* bk = (const float*)d_in[5];
    const float* Wv = (const float*)d_in[6];
    const float* bv = (const float*)d_in[7];
    const float* Wo = (const float*)d_in[8];
    const float* bo = (const float*)d_in[9];
    const int*   nf = (const int*)d_in[10];
    float* out = (float*)d_out;

    __half *Ph, *Lh, *Qd, *KVd, *Ad, *WtQ, *WtKV, *WtO;
    float *bkv;
    cudaGetSymbolAddress((void**)&Ph,   g_Ph);
    cudaGetSymbolAddress((void**)&Lh,   g_Lh);
    cudaGetSymbolAddress((void**)&Qd,   g_Q);
    cudaGetSymbolAddress((void**)&KVd,  g_KV);
    cudaGetSymbolAddress((void**)&Ad,   g_attn);
    cudaGetSymbolAddress((void**)&WtQ,  g_WtQ);
    cudaGetSymbolAddress((void**)&WtKV, g_WtKV);
    cudaGetSymbolAddress((void**)&WtO,  g_WtO);
    cudaGetSymbolAddress((void**)&bkv,  g_bkv);

    cudaFuncSetAttribute(gemm_f16<__half>, cudaFuncAttributeMaxDynamicSharedMemorySize, GEMM_SMEM);
    cudaFuncSetAttribute(gemm_f16<float>,  cudaFuncAttributeMaxDynamicSharedMemorySize, GEMM_SMEM);
    cudaFuncSetAttribute(attn_kernel, cudaFuncAttributeMaxDynamicSharedMemorySize, ATTN_SMEM);

    // 0) prep (3 launches)
    transpose_all_kernel<<<dim3(32, 32, 3), dim3(32, 8)>>>(Wq, Wk, Wv, Wo, WtQ, WtKV, WtO);
    rope_table_kernel<<<(NF_MAX * 32) / 256, 256>>>(nf, bk, bv);
    int np4 = B_ * LQ_ * D_ / 4;
    int nl4 = B_ * LKV_ * D_ / 4;
    cvt_both_kernel<<<(np4 + nl4 + 255) / 256, 256>>>(patches, latents, Ph, Lh, np4, np4 + nl4);

    // 1) Q projection (half out)
    gemm_f16<__half><<<dim3(D_ / 128, (B_ * LQ_) / 128), 256, GEMM_SMEM>>>(
        Ph, WtQ, bq, Qd, B_ * LQ_, D_, D_);

    // 2) fused K|V projection (half out, N=512)
    gemm_f16<__half><<<dim3(512 / 128, (B_ * LKV_) / 128), 256, GEMM_SMEM>>>(
        Lh, WtKV, bkv, KVd, B_ * LKV_, 512, D_);

    // 2b) kv_prep: rope'd K + V^T pre-swizzled blobs (16 CTAs)
    kv_prep_kernel<<<dim3(KVH_, B_), 256>>>(KVd, nf);

    // 3) attention (fp16 mma; P in registers; 2 CTAs/SM)
    dim3 ga(LQ_ / 128, H_, B_);
    attn_kernel<<<ga, 256, ATTN_SMEM>>>(Qd, Ad, nf);

    // 4) output projection (float out)
    gemm_f16<float><<<dim3(D_ / 128, (B_ * LQ_) / 128), 256, GEMM_SMEM>>>(
        Ad, WtO, bo, out, B_ * LQ_, D_, D_);
}

// round 16
// speedup vs baseline: 1.5506x; 1.0438x over previous
#include <cuda_runtime.h>
#include <cuda_fp16.h>
#include <math.h>
#include <stdint.h>

#define B_    4
#define LQ_   4096
#define LKV_  256
#define D_    1024
#define H_    16
#define KVH_  4
#define HD_   64
#define NF_MAX 4096

// ---------------- scratch (device globals; no allocation allowed) ----------
__device__ __half g_Ph[(size_t)B_ * LQ_ * D_];          // fp16 patches
__device__ __half g_Lh[(size_t)B_ * LKV_ * D_];         // fp16 latents
__device__ __half g_Q[(size_t)B_ * LQ_ * D_];           // fp16 Q
__device__ __half g_KV[(size_t)B_ * LKV_ * 512];        // fused K|V
__device__ __half g_Kr[(size_t)B_ * KVH_ * 16384];      // rope'd K, pre-swizzled blobs
__device__ __half g_Vt[(size_t)B_ * KVH_ * 16384];      // V^T, pre-swizzled blobs
__device__ __half g_attn[(size_t)B_ * LQ_ * D_];        // fp16 attn out
__device__ __half g_WtQ[(size_t)D_ * D_];               // W^T [N][K] fp16
__device__ __half g_WtKV[(size_t)512 * D_];             // [Wk^T ; Wv^T]
__device__ __half g_WtO[(size_t)D_ * D_];
__device__ float  g_bkv[512];                            // bk | bv
__device__ float  g_rope[2 * NF_MAX * 32];              // cos | sin

// ---------------- helpers ---------------------------------------------------
__device__ __forceinline__ uint32_t smem_u32(const void* p) {
    uint32_t a;
    asm("{ .reg .u64 t; cvta.to.shared.u64 t, %1; cvt.u32.u64 %0, t; }"
        : "=r"(a) : "l"(p));
    return a;
}
__device__ __forceinline__ uint32_t sw128(uint32_t off) {
    return off ^ ((off >> 3) & 0x70);
}

#define CP_A16(d, s) \
    asm volatile("cp.async.cg.shared.global [%0], [%1], 16;" :: "r"(d), "l"(s) : "memory")
#define CP_COMMIT() asm volatile("cp.async.commit_group;" ::: "memory")
#define CP_WAIT0()  asm volatile("cp.async.wait_group 0;" ::: "memory")
#define LDSM4(r, addr) \
    asm volatile("ldmatrix.sync.aligned.m8n8.x4.shared.b16 {%0,%1,%2,%3}, [%4];" \
        : "=r"((r)[0]), "=r"((r)[1]), "=r"((r)[2]), "=r"((r)[3]) : "r"(addr))
#define MMA_F16(d, a0, a1, a2, a3, b0, b1) \
    asm volatile("mma.sync.aligned.m16n8k16.row.col.f32.f16.f16.f32 " \
        "{%0,%1,%2,%3}, {%4,%5,%6,%7}, {%8,%9}, {%0,%1,%2,%3};" \
        : "+f"((d)[0]), "+f"((d)[1]), "+f"((d)[2]), "+f"((d)[3]) \
        : "r"(a0), "r"(a1), "r"(a2), "r"(a3), "r"(b0), "r"(b1))

__device__ __forceinline__ void store2(float* p, float x, float y) {
    *(float2*)p = make_float2(x, y);
}
__device__ __forceinline__ void store2(__half* p, float x, float y) {
    *(__half2*)p = __floats2half2_rn(x, y);
}
__device__ __forceinline__ uint32_t pack_h2(float x, float y) {
    __half2 h = __floats2half2_rn(x, y);
    return *(uint32_t*)&h;
}

// ---------------------------------------------------------------------------
// Mega-prep: one launch, z-dispatch.
//  z=0: Wq -> WtQ transpose    z=1: Wo -> WtO    z=2: Wk|Wv -> WtKV
//  z=3: fp32->fp16 cvt of patches+latents (grid-stride)
//  z=4: rope table + bias concat
// block (32,8) = 256 threads.
// ---------------------------------------------------------------------------
__global__ void mega_prep_kernel(const float* __restrict__ Wq, const float* __restrict__ Wk,
                                 const float* __restrict__ Wv, const float* __restrict__ Wo,
                                 const float* __restrict__ patches, const float* __restrict__ latents,
                                 const float* __restrict__ bk, const float* __restrict__ bv,
                                 const int* __restrict__ nf_ptr)
{
    int z = blockIdx.z;
    int tx = threadIdx.x, ty = threadIdx.y;
    int tid256 = ty * 32 + tx;

    if (z <= 2) {
        __shared__ float t[32][33];
        const float* W;
        __half* Wt;
        int N, nb, rowoff = 0;
        if (z == 0)      { W = Wq; Wt = g_WtQ; N = D_; nb = blockIdx.x * 32; }
        else if (z == 1) { W = Wo; Wt = g_WtO; N = D_; nb = blockIdx.x * 32; }
        else {
            if (blockIdx.x >= 16) return;
            if (blockIdx.x < 8) { W = Wk; rowoff = 0;   nb = blockIdx.x * 32; }
            else                { W = Wv; rowoff = 256; nb = (blockIdx.x - 8) * 32; }
            Wt = g_WtKV; N = KVH_ * HD_;
        }
        int kb = blockIdx.y * 32;
#pragma unroll
        for (int i = 0; i < 32; i += 8)
            t[ty + i][tx] = W[(size_t)(kb + ty + i) * N + nb + tx];
        __syncthreads();
#pragma unroll
        for (int i = 0; i < 32; i += 8)
            Wt[(size_t)(rowoff + nb + ty + i) * D_ + kb + tx] = __float2half_rn(t[tx][ty + i]);
        return;
    }

    if (z == 3) {
        const int np4 = B_ * LQ_ * D_ / 4;
        const int nl4 = B_ * LKV_ * D_ / 4;
        const int tot4 = np4 + nl4;
        int stride = 1024 * 256;                        // 32x32 blocks x 256 thr
        int g = (blockIdx.y * 32 + blockIdx.x) * 256 + tid256;
        for (int i = g; i < tot4; i += stride) {
            const float* in;
            __half* out;
            int j;
            if (i < np4) { in = patches; out = g_Ph; j = i; }
            else         { in = latents; out = g_Lh; j = i - np4; }
            float4 v = reinterpret_cast<const float4*>(in)[j];
            reinterpret_cast<__half2*>(out)[2 * j]     = __floats2half2_rn(v.x, v.y);
            reinterpret_cast<__half2*>(out)[2 * j + 1] = __floats2half2_rn(v.z, v.w);
        }
        return;
    }

    // z == 4: rope table + bias concat
    int bid = blockIdx.y * 32 + blockIdx.x;
    if (bid == 0) g_bkv[tid256] = bk[tid256];
    if (bid == 1) g_bkv[256 + tid256] = bv[tid256];
    int nf = *nf_ptr;
    if (nf <= 1 || nf > NF_MAX) return;
    int idx = bid * 256 + tid256;
    if (idx >= nf * 32) return;
    int j = idx & 31, pos = idx >> 5;
    float inv = powf(10000.0f, -(float)(2 * j) / 64.0f);
    float th = (float)pos * inv;
    g_rope[idx] = cosf(th);
    g_rope[NF_MAX * 32 + idx] = sinf(th);
}

// ---------------------------------------------------------------------------
// kv_prep (unchanged): pre-swizzled rope'd K and V^T blobs per (b,kvh).
// ---------------------------------------------------------------------------
__global__ void kv_prep_kernel(const __half* __restrict__ KV, const int* __restrict__ nf_ptr)
{
    int kvh = blockIdx.x, b = blockIdx.y;
    int tid = threadIdx.x;
    int nf = *nf_ptr;
    bool rope = (nf > 1) && (nf <= NF_MAX);
    int kdiv = rope ? (LKV_ / nf) : 1;
    char* kr = (char*)(g_Kr + ((size_t)(b * KVH_ + kvh)) * 16384);
    char* vt = (char*)(g_Vt + ((size_t)(b * KVH_ + kvh)) * 16384);

    for (int u = tid; u < 512; u += 256) {
        int row = u >> 1, part = u & 1;
        const __half* src = KV + (size_t)(b * LKV_ + row) * 512 + kvh * HD_;
        int pos = rope ? (row / kdiv) : 0;
        const float* ct = g_rope + pos * 32;
        const float* st = g_rope + NF_MAX * 32 + pos * 32;
#pragma unroll
        for (int jj = 0; jj < 4; jj++) {
            int j = part * 16 + jj * 4;
            __half2 u0 = *(const __half2*)(src + j);
            __half2 u1 = *(const __half2*)(src + j + 2);
            __half2 v0 = *(const __half2*)(src + j + 32);
            __half2 v1 = *(const __half2*)(src + j + 34);
            float a1[4] = { __low2float(u0), __high2float(u0), __low2float(u1), __high2float(u1) };
            float a2[4] = { __low2float(v0), __high2float(v0), __low2float(v1), __high2float(v1) };
            float y1[4], y2[4];
#pragma unroll
            for (int e = 0; e < 4; e++) {
                float c = 1.f, s = 0.f;
                if (rope) { c = ct[j + e], s = st[j + e]; }
                y1[e] = a1[e] * c - a2[e] * s;
                y2[e] = a2[e] * c + a1[e] * s;
            }
            uint32_t o0 = sw128((uint32_t)(row * 128 + j * 2));
            uint32_t o1 = sw128((uint32_t)(row * 128 + (j + 32) * 2));
            ((__half2*)(kr + o0))[0] = __floats2half2_rn(y1[0], y1[1]);
            ((__half2*)(kr + o0))[1] = __floats2half2_rn(y1[2], y1[3]);
            ((__half2*)(kr + o1))[0] = __floats2half2_rn(y2[0], y2[1]);
            ((__half2*)(kr + o1))[1] = __floats2half2_rn(y2[2], y2[3]);
        }
    }

#pragma unroll
    for (int it = 0; it < 8; it++) {
        int idx = it * 256 + tid;
        int kv = idx >> 3, c8 = idx & 7;
        const __half* src = KV + (size_t)(b * LKV_ + kv) * 512 + 256 + kvh * HD_ + c8 * 8;
        uint4 raw = *(const uint4*)src;
        const __half* hv = (const __half*)&raw;
        char* base = vt + (kv >> 6) * 8192;
        int kcol = (kv & 63) * 2;
#pragma unroll
        for (int e = 0; e < 8; e++) {
            int d = c8 * 8 + e;
            *(__half*)(base + sw128((uint32_t)(d * 128 + kcol))) = hv[e];
        }
    }
}

// ---------------------------------------------------------------------------
// fp16 mma.sync GEMM body (EXACT round-15 proven mainloop — FROZEN).
// CTA 128x128, 8 warps (64x32), BK=64 halves, 2-buffer cp.async,
// single __syncthreads per iteration.
// ---------------------------------------------------------------------------
#define GEMM_SMEM (1024 + 4 * 16384)

__device__ __forceinline__ void load_tile(const __half* Ag, const __half* Bg, int K,
                                          uint32_t aBuf, uint32_t bBuf, int tid)
{
#pragma unroll
    for (int j = 0; j < 4; j++) {
        int idx = j * 256 + tid;
        int row = idx >> 3, k8 = idx & 7;
        uint32_t off = sw128((uint32_t)(row * 128 + k8 * 16));
        CP_A16(aBuf + off, Ag + (size_t)row * K + k8 * 8);
        CP_A16(bBuf + off, Bg + (size_t)row * K + k8 * 8);
    }
}

template <typename OutT>
__device__ __forceinline__ void gemm_body(const __half* __restrict__ A,
                                          const __half* __restrict__ Bt,
                                          const float* __restrict__ bias,
                                          OutT* __restrict__ C,
                                          int N, int K, int bx, int by,
                                          char* smraw)
{
    uint32_t base = smem_u32(smraw);
    uint32_t data = (base + 1023u) & ~1023u;

    int tid = threadIdx.x, lane = tid & 31, wid = tid >> 5;
    int wm = (wid >> 2) * 64;
    int wn = (wid & 3) * 32;

    const __half* Ag = A  + (size_t)by * 128 * K;
    const __half* Bg = Bt + (size_t)bx * 128 * K;

    float acc[4][4][4];
#pragma unroll
    for (int i = 0; i < 4; i++)
#pragma unroll
        for (int j = 0; j < 4; j++)
#pragma unroll
            for (int k = 0; k < 4; k++) acc[i][j][k] = 0.f;

    int T = K >> 6;
    load_tile(Ag, Bg, K, data, data + 16384u, tid);
    CP_COMMIT();

    int lmat = lane >> 3, lrow = lane & 7;
    int frow = ((lmat & 2) ? 8 : 0) + lrow;
    int fcol = (lmat & 1) * 16;

    for (int t = 0; t < T; ++t) {
        CP_WAIT0();
        __syncthreads();

        if (t + 1 < T) {
            uint32_t nb = data + (uint32_t)((t + 1) & 1) * 32768u;
            load_tile(Ag + (t + 1) * 64, Bg + (t + 1) * 64, K, nb, nb + 16384u, tid);
            CP_COMMIT();
        }

        uint32_t aB = data + (uint32_t)(t & 1) * 32768u;
        uint32_t bB = aB + 16384u;
#pragma unroll
        for (int kk = 0; kk < 4; ++kk) {
            uint32_t af[4][4], bf[2][4];
#pragma unroll
            for (int mi = 0; mi < 4; ++mi) {
                uint32_t addr = aB + sw128((uint32_t)((wm + mi * 16 + frow) * 128 + kk * 32 + fcol));
                LDSM4(af[mi], addr);
            }
#pragma unroll
            for (int nj = 0; nj < 2; ++nj) {
                uint32_t addr = bB + sw128((uint32_t)((wn + nj * 16 + frow) * 128 + kk * 32 + fcol));
                LDSM4(bf[nj], addr);
            }
#pragma unroll
            for (int mi = 0; mi < 4; ++mi)
#pragma unroll
                for (int ni = 0; ni < 4; ++ni) {
                    int nj = ni >> 1, lh = (ni & 1) * 2;
                    MMA_F16(acc[mi][ni],
                            af[mi][0], af[mi][2], af[mi][1], af[mi][3],
                            bf[nj][lh], bf[nj][lh + 1]);
                }
        }
    }

    int rbase = by * 128 + wm + (lane >> 2);
    int cbase = bx * 128 + wn + (lane & 3) * 2;
#pragma unroll
    for (int mi = 0; mi < 4; ++mi) {
#pragma unroll
        for (int ni = 0; ni < 4; ++ni) {
            int c = cbase + ni * 8;
            float2 bv = *(const float2*)(bias + c);
            int r0 = rbase + mi * 16;
            store2(C + (size_t)r0 * N + c, acc[mi][ni][0] + bv.x, acc[mi][ni][1] + bv.y);
            store2(C + (size_t)(r0 + 8) * N + c, acc[mi][ni][2] + bv.x, acc[mi][ni][3] + bv.y);
        }
    }
}

// Fused Q-proj (1024 CTAs) + KV-proj (32 CTAs) in one launch, 1D grid 1056.
__global__ __launch_bounds__(256, 2)
void gemm_qkv(const __half* __restrict__ Ph, const __half* __restrict__ Lh,
              const float* __restrict__ bq, const float* __restrict__ bkv,
              __half* __restrict__ Qd, __half* __restrict__ KVd)
{
    extern __shared__ char smraw[];
    int bid = blockIdx.x;
    const __half *A, *Bt;
    const float* bias;
    __half* C;
    int N, bx, by;
    if (bid < 1024) {
        A = Ph; Bt = g_WtQ; bias = bq; C = Qd;
        N = D_; bx = bid & 7; by = bid >> 3;
    } else {
        int r = bid - 1024;
        A = Lh; Bt = g_WtKV; bias = bkv; C = KVd;
        N = 512; bx = r & 3; by = r >> 2;
    }
    gemm_body<__half>(A, Bt, bias, C, N, D_, bx, by, smraw);
}

// O-projection (float out), standard 2D grid.
__global__ __launch_bounds__(256, 2)
void gemm_o(const __half* __restrict__ Ad, const float* __restrict__ bo,
            float* __restrict__ out)
{
    extern __shared__ char smraw[];
    gemm_body<float>(Ad, g_WtO, bo, out, D_, D_, blockIdx.x, blockIdx.y, smraw);
}

// ---------------------------------------------------------------------------
// fp16 MMA flash attention (EXACT round-14 version — FROZEN).
// ---------------------------------------------------------------------------
#define QS_OFF 0u
#define KS_OFF 16384u
#define VT_OFF 49152u
#define ATTN_SMEM 81920

__global__ __launch_bounds__(256, 2)
void attn_kernel(const __half* __restrict__ Q, __half* __restrict__ O,
                 const int* __restrict__ nf_ptr)
{
    extern __shared__ char sm[];
    uint32_t smb = smem_u32(sm);

    int tid = threadIdx.x, l = tid & 31, w = tid >> 5;
    int b = blockIdx.z, h = blockIdx.y, qt = blockIdx.x;
    int kvh = h >> 2;
    int nf = *nf_ptr;
    bool rope = (nf > 1) && (nf <= NF_MAX);
    int qdiv = rope ? (LQ_ / nf) : 1;

    const char* krb = (const char*)(g_Kr + ((size_t)(b * KVH_ + kvh)) * 16384);
    const char* vtb = (const char*)(g_Vt + ((size_t)(b * KVH_ + kvh)) * 16384);
#pragma unroll
    for (int it = 0; it < 8; it++) {
        uint32_t off = (uint32_t)(it * 256 + tid) * 16u;
        CP_A16(smb + KS_OFF + off, krb + off);
        CP_A16(smb + VT_OFF + off, vtb + off);
    }
    CP_COMMIT();

    const float QSCALE = 0.125f * 1.4426950408889634f;
    {
        int row = tid >> 1, part = tid & 1;
        int qglob = qt * 128 + row;
        const __half* src = Q + ((size_t)(b * LQ_ + qglob)) * D_ + h * HD_;
        int pos = rope ? (qglob / qdiv) : 0;
        const float* ct = g_rope + pos * 32;
        const float* st = g_rope + NF_MAX * 32 + pos * 32;
#pragma unroll
        for (int jj = 0; jj < 4; jj++) {
            int j = part * 16 + jj * 4;
            __half2 u0 = *(const __half2*)(src + j);
            __half2 u1 = *(const __half2*)(src + j + 2);
            __half2 v0 = *(const __half2*)(src + j + 32);
            __half2 v1 = *(const __half2*)(src + j + 34);
            float a1[4] = { __low2float(u0), __high2float(u0), __low2float(u1), __high2float(u1) };
            float a2[4] = { __low2float(v0), __high2float(v0), __low2float(v1), __high2float(v1) };
            float y1[4], y2[4];
#pragma unroll
            for (int e = 0; e < 4; e++) {
                float c = 1.f, s = 0.f;
                if (rope) { c = ct[j + e], s = st[j + e]; }
                y1[e] = (a1[e] * c - a2[e] * s) * QSCALE;
                y2[e] = (a2[e] * c + a1[e] * s) * QSCALE;
            }
            uint32_t o0 = QS_OFF + sw128((uint32_t)(row * 128 + j * 2));
            uint32_t o1 = QS_OFF + sw128((uint32_t)(row * 128 + (j + 32) * 2));
            ((__half2*)(sm + o0))[0] = __floats2half2_rn(y1[0], y1[1]);
            ((__half2*)(sm + o0))[1] = __floats2half2_rn(y1[2], y1[3]);
            ((__half2*)(sm + o1))[0] = __floats2half2_rn(y2[0], y2[1]);
            ((__half2*)(sm + o1))[1] = __floats2half2_rn(y2[2], y2[3]);
        }
    }
    CP_WAIT0();
    __syncthreads();

    int lmat = l >> 3, lrow = l & 7;
    int frow = ((lmat & 2) ? 8 : 0) + lrow;
    int fcol = (lmat & 1) * 16;
    int mrow = w * 16 + frow;

    uint32_t qf[4][4];
#pragma unroll
    for (int kk = 0; kk < 4; kk++) {
        uint32_t a = smb + QS_OFF + sw128((uint32_t)(mrow * 128 + kk * 32 + fcol));
        LDSM4(qf[kk], a);
    }

    float oacc[8][4];
#pragma unroll
    for (int i = 0; i < 8; i++)
#pragma unroll
        for (int j = 0; j < 4; j++) oacc[i][j] = 0.f;
    float rs0 = 0.f, rs1 = 0.f;

#pragma unroll
    for (int cc = 0; cc < 4; cc++) {
        float sc[8][4];
#pragma unroll
        for (int i = 0; i < 8; i++)
#pragma unroll
            for (int j = 0; j < 4; j++) sc[i][j] = 0.f;

#pragma unroll
        for (int ng = 0; ng < 4; ng++) {
            int kvrow = cc * 64 + ng * 16 + frow;
#pragma unroll
            for (int kk = 0; kk < 4; kk++) {
                uint32_t bf[4];
                uint32_t a = smb + KS_OFF + sw128((uint32_t)(kvrow * 128 + kk * 32 + fcol));
                LDSM4(bf, a);
                MMA_F16(sc[2 * ng],     qf[kk][0], qf[kk][2], qf[kk][1], qf[kk][3], bf[0], bf[1]);
                MMA_F16(sc[2 * ng + 1], qf[kk][0], qf[kk][2], qf[kk][1], qf[kk][3], bf[2], bf[3]);
            }
        }

        uint32_t pk[4][4];
#pragma unroll
        for (int kt = 0; kt < 4; kt++) {
            float p00 = exp2f(sc[2 * kt][0]);
            float p01 = exp2f(sc[2 * kt][1]);
            float p02 = exp2f(sc[2 * kt][2]);
            float p03 = exp2f(sc[2 * kt][3]);
            float p10 = exp2f(sc[2 * kt + 1][0]);
            float p11 = exp2f(sc[2 * kt + 1][1]);
            float p12 = exp2f(sc[2 * kt + 1][2]);
            float p13 = exp2f(sc[2 * kt + 1][3]);
            rs0 += (p00 + p01) + (p10 + p11);
            rs1 += (p02 + p03) + (p12 + p13);
            pk[kt][0] = pack_h2(p00, p01);
            pk[kt][1] = pack_h2(p02, p03);
            pk[kt][2] = pack_h2(p10, p11);
            pk[kt][3] = pack_h2(p12, p13);
        }

#pragma unroll
        for (int dg = 0; dg < 4; dg++) {
#pragma unroll
            for (int kt = 0; kt < 4; kt++) {
                uint32_t bf[4];
                uint32_t a = smb + VT_OFF + (uint32_t)cc * 8192u
                           + sw128((uint32_t)((dg * 16 + frow) * 128 + kt * 32 + fcol));
                LDSM4(bf, a);
                MMA_F16(oacc[2 * dg],     pk[kt][0], pk[kt][1], pk[kt][2], pk[kt][3], bf[0], bf[1]);
                MMA_F16(oacc[2 * dg + 1], pk[kt][0], pk[kt][1], pk[kt][2], pk[kt][3], bf[2], bf[3]);
            }
        }
    }

    rs0 += __shfl_xor_sync(0xFFFFFFFFu, rs0, 1);
    rs0 += __shfl_xor_sync(0xFFFFFFFFu, rs0, 2);
    rs1 += __shfl_xor_sync(0xFFFFFFFFu, rs1, 1);
    rs1 += __shfl_xor_sync(0xFFFFFFFFu, rs1, 2);
    float inv0 = 1.0f / rs0, inv1 = 1.0f / rs1;

    int q0 = qt * 128 + w * 16 + (l >> 2);
    __half* o0 = O + ((size_t)(b * LQ_ + q0)) * D_ + h * HD_;
    __half* o1 = o0 + 8 * D_;
#pragma unroll
    for (int nt = 0; nt < 8; nt++) {
        int dcol = nt * 8 + 2 * (l & 3);
        *(__half2*)(o0 + dcol) = __floats2half2_rn(oacc[nt][0] * inv0, oacc[nt][1] * inv0);
        *(__half2*)(o1 + dcol) = __floats2half2_rn(oacc[nt][2] * inv1, oacc[nt][3] * inv1);
    }
}

// ---------------------------------------------------------------------------
extern "C" void kernel_launch(void* const* d_in, const int* in_sizes, int n_in,
                              void* d_out, int out_size)
{
    const float* patches = (const float*)d_in[0];
    const float* latents = (const float*)d_in[1];
    const float* Wq = (const float*)d_in[2];
    const float* bq = (const float*)d_in[3];
    const float* Wk = (const float*)d_in[4];
    const float* bk = (const float*)d_in[5];
    const float* Wv = (const float*)d_in[6];
    const float* bv = (const float*)d_in[7];
    const float* Wo = (const float*)d_in[8];
    const float* bo = (const float*)d_in[9];
    const int*   nf = (const int*)d_in[10];
    float* out = (float*)d_out;

    __half *Ph, *Lh, *Qd, *KVd, *Ad;
    float *bkv;
    cudaGetSymbolAddress((void**)&Ph,   g_Ph);
    cudaGetSymbolAddress((void**)&Lh,   g_Lh);
    cudaGetSymbolAddress((void**)&Qd,   g_Q);
    cudaGetSymbolAddress((void**)&KVd,  g_KV);
    cudaGetSymbolAddress((void**)&Ad,   g_attn);
    cudaGetSymbolAddress((void**)&bkv,  g_bkv);

    cudaFuncSetAttribute(gemm_qkv, cudaFuncAttributeMaxDynamicSharedMemorySize, GEMM_SMEM);
    cudaFuncSetAttribute(gemm_o,   cudaFuncAttributeMaxDynamicSharedMemorySize, GEMM_SMEM);
    cudaFuncSetAttribute(attn_kernel, cudaFuncAttributeMaxDynamicSharedMemorySize, ATTN_SMEM);

    // 0) mega-prep: weight transposes + activations cvt + rope table + biases
    mega_prep_kernel<<<dim3(32, 32, 5), dim3(32, 8)>>>(
        Wq, Wk, Wv, Wo, patches, latents, bk, bv, nf);

    // 1) fused Q + KV projections (1056 CTAs)
    gemm_qkv<<<1056, 256, GEMM_SMEM>>>(Ph, Lh, bq, bkv, Qd, KVd);

    // 2) kv_prep: rope'd K + V^T pre-swizzled blobs (16 CTAs)
    kv_prep_kernel<<<dim3(KVH_, B_), 256>>>(KVd, nf);

    // 3) attention (fp16 mma; P in registers; 2 CTAs/SM)
    dim3 ga(LQ_ / 128, H_, B_);
    attn_kernel<<<ga, 256, ATTN_SMEM>>>(Qd, Ad, nf);

    // 4) output projection (float out)
    gemm_o<<<dim3(D_ / 128, (B_ * LQ_) / 128), 256, GEMM_SMEM>>>(Ad, bo, out);
}